// round 2
// baseline (speedup 1.0000x reference)
#include <cuda_runtime.h>

#define NH   6
#define HS   24
#define NE   144
#define TT   128
#define BB   256
#define MTOT (BB*TT)        // 32768 tokens

// ---------------- device scratch (allocation-free) ----------------
__device__ float g_q[MTOT*NE];
__device__ float g_k[MTOT*NE];
__device__ float g_v[MTOT*NE];
__device__ float g_ctx[MTOT*NE];

// =====================================================================
// Kernel A: fused QKV GEMM.  out[m,n] = sum_k x[m,k] * W[k,n]
// grid (512 Mtiles of 64, 3 Ntiles of 48, z in {q,k,v}), 256 threads.
// =====================================================================
__global__ __launch_bounds__(256) void qkv_kernel(
    const float* __restrict__ x,
    const float* __restrict__ Wq,
    const float* __restrict__ Wk,
    const float* __restrict__ Wv)
{
    __shared__ __align__(16) float Ast[48][68];   // [k][row] transposed, padded
    __shared__ __align__(16) float Bs [48][48];   // [k][col]

    const int mt = blockIdx.x, nt = blockIdx.y, z = blockIdx.z;
    const float* W = (z == 0) ? Wq : ((z == 1) ? Wk : Wv);
    float* outp    = (z == 0) ? g_q : ((z == 1) ? g_k : g_v);

    const int r0 = mt * 64, c0 = nt * 48;
    const int tid = threadIdx.x;
    const int tx = tid & 15, ty = tid >> 4;

    float acc[4][3] = {};

    for (int kc = 0; kc < NE; kc += 48) {
        for (int i = tid; i < 64 * 48; i += 256) {
            int r = i / 48, k = i % 48;
            Ast[k][r] = x[(r0 + r) * NE + kc + k];
        }
        for (int i = tid; i < 48 * 48; i += 256) {
            int k = i / 48, c = i % 48;
            Bs[k][c] = W[(kc + k) * NE + c0 + c];
        }
        __syncthreads();
        #pragma unroll 8
        for (int k = 0; k < 48; ++k) {
            float4 af = *reinterpret_cast<const float4*>(&Ast[k][ty * 4]);
            float a[4] = {af.x, af.y, af.z, af.w};
            float b[3] = {Bs[k][tx * 3 + 0], Bs[k][tx * 3 + 1], Bs[k][tx * 3 + 2]};
            #pragma unroll
            for (int i = 0; i < 4; ++i)
                #pragma unroll
                for (int j = 0; j < 3; ++j)
                    acc[i][j] += a[i] * b[j];
        }
        __syncthreads();
    }
    #pragma unroll
    for (int i = 0; i < 4; ++i)
        #pragma unroll
        for (int j = 0; j < 3; ++j)
            outp[(r0 + ty * 4 + i) * NE + c0 + tx * 3 + j] = acc[i][j];
}

// =====================================================================
// Kernel B: attention per (b,h).  1536 blocks, 512 threads, dyn smem.
//   S  = Q @ (scale*K)^T                      (128x128x24 GEMM)
//   S[t][t-j] += (Q @ R^T)[t][j]   (rel term) (128x128x24 GEMM)
//   row softmax (causal), masked entries -> 0
//   ctx = S @ V                               (128x128x24 -> 128x24)
// =====================================================================
#define LDT  132     // row stride of transposed Qt/Kt/Rt  [24][132]
#define LDV  25      // row stride of Vs                   [128][25]
#define LDSS 132     // row stride of S                    [128][132]
#define ATTN_SMEM ((3*24*LDT + 128*LDV + 128*LDSS) * 4)   // 118400 B

__global__ __launch_bounds__(512) void attn_kernel(const float* __restrict__ rel_table)
{
    extern __shared__ __align__(16) float sm[];
    float* Qt = sm;                    // [24][132]  Qt[d][t]
    float* Kt = Qt + 24 * LDT;         // [24][132]  Kt[d][s] (pre-scaled)
    float* Rt = Kt + 24 * LDT;         // [24][132]  Rt[d][j], j = t-s
    float* Vs = Rt + 24 * LDT;         // [128][25]  Vs[s][c]
    float* S  = Vs + 128 * LDV;        // [128][132]

    const int bh = blockIdx.x;
    const int b = bh / NH, h = bh % NH;
    const int base = b * (TT * NE) + h * (TT * HS);   // contiguous 3072-float chunk
    const int tid = threadIdx.x;
    const float scale = 0.2041241452319315f;          // 1/sqrt(24)

    for (int i = tid; i < TT * HS; i += 512) {
        int t = i / HS, d = i % HS;
        Qt[d * LDT + t] = g_q[base + i];
        Kt[d * LDT + t] = g_k[base + i] * scale;
        Rt[d * LDT + t] = rel_table[(TT - 1) * HS + i];   // rows 127..254
        Vs[t * LDV + d] = g_v[base + i];
    }
    __syncthreads();

    const int tx = tid & 31, ty = tid >> 5;
    const int t0 = ty * 8, s0 = tx * 4;

    // ---- stage 1: S = Q @ K'^T ----
    {
        float acc[8][4] = {};
        #pragma unroll
        for (int d = 0; d < 24; ++d) {
            float4 bv = *reinterpret_cast<const float4*>(&Kt[d * LDT + s0]);
            float4 a0 = *reinterpret_cast<const float4*>(&Qt[d * LDT + t0]);
            float4 a1 = *reinterpret_cast<const float4*>(&Qt[d * LDT + t0 + 4]);
            float av[8] = {a0.x, a0.y, a0.z, a0.w, a1.x, a1.y, a1.z, a1.w};
            #pragma unroll
            for (int i = 0; i < 8; ++i) {
                acc[i][0] += av[i] * bv.x;  acc[i][1] += av[i] * bv.y;
                acc[i][2] += av[i] * bv.z;  acc[i][3] += av[i] * bv.w;
            }
        }
        #pragma unroll
        for (int i = 0; i < 8; ++i)
            *reinterpret_cast<float4*>(&S[(t0 + i) * LDSS + s0]) =
                make_float4(acc[i][0], acc[i][1], acc[i][2], acc[i][3]);
    }
    __syncthreads();

    // ---- stage 2: P = Q @ R^T, scatter-add S[t][t-j] += P[t][j] ----
    {
        float acc[8][4] = {};
        #pragma unroll
        for (int d = 0; d < 24; ++d) {
            float4 bv = *reinterpret_cast<const float4*>(&Rt[d * LDT + s0]);
            float4 a0 = *reinterpret_cast<const float4*>(&Qt[d * LDT + t0]);
            float4 a1 = *reinterpret_cast<const float4*>(&Qt[d * LDT + t0 + 4]);
            float av[8] = {a0.x, a0.y, a0.z, a0.w, a1.x, a1.y, a1.z, a1.w};
            #pragma unroll
            for (int i = 0; i < 8; ++i) {
                acc[i][0] += av[i] * bv.x;  acc[i][1] += av[i] * bv.y;
                acc[i][2] += av[i] * bv.z;  acc[i][3] += av[i] * bv.w;
            }
        }
        #pragma unroll
        for (int i = 0; i < 8; ++i) {
            int t = t0 + i;
            #pragma unroll
            for (int j = 0; j < 4; ++j) {
                int s = t - (s0 + j);              // unique (t,s) per (t,j): no races
                if (s >= 0) S[t * LDSS + s] += acc[i][j];
            }
        }
    }
    __syncthreads();

    // ---- softmax: warp per 8 rows, causal mask, masked -> 0 ----
    {
        const int w = tid >> 5, lane = tid & 31;
        for (int r = 0; r < 8; ++r) {
            int t = w * 8 + r;
            float x0 = (lane      <= t) ? S[t * LDSS + lane     ] : -1e30f;
            float x1 = (lane + 32 <= t) ? S[t * LDSS + lane + 32] : -1e30f;
            float x2 = (lane + 64 <= t) ? S[t * LDSS + lane + 64] : -1e30f;
            float x3 = (lane + 96 <= t) ? S[t * LDSS + lane + 96] : -1e30f;
            float m = fmaxf(fmaxf(x0, x1), fmaxf(x2, x3));
            #pragma unroll
            for (int o = 16; o > 0; o >>= 1)
                m = fmaxf(m, __shfl_xor_sync(0xffffffffu, m, o));
            float e0 = (lane      <= t) ? __expf(x0 - m) : 0.f;
            float e1 = (lane + 32 <= t) ? __expf(x1 - m) : 0.f;
            float e2 = (lane + 64 <= t) ? __expf(x2 - m) : 0.f;
            float e3 = (lane + 96 <= t) ? __expf(x3 - m) : 0.f;
            float ssum = e0 + e1 + e2 + e3;
            #pragma unroll
            for (int o = 16; o > 0; o >>= 1)
                ssum += __shfl_xor_sync(0xffffffffu, ssum, o);
            float inv = 1.0f / ssum;
            S[t * LDSS + lane     ] = e0 * inv;
            S[t * LDSS + lane + 32] = e1 * inv;
            S[t * LDSS + lane + 64] = e2 * inv;
            S[t * LDSS + lane + 96] = e3 * inv;
        }
    }
    __syncthreads();

    // ---- stage 3: ctx = S @ V, write to g_ctx in (B,T,H*hs) layout ----
    {
        const int tx3 = tid & 7, ty3 = tid >> 3;    // cols 3*tx3, rows 2*ty3
        const int rt = ty3 * 2, ct = tx3 * 3;
        float acc[2][3] = {};
        #pragma unroll 4
        for (int k = 0; k < TT; ++k) {
            float a0 = S[(rt    ) * LDSS + k];
            float a1 = S[(rt + 1) * LDSS + k];
            float b0 = Vs[k * LDV + ct    ];
            float b1 = Vs[k * LDV + ct + 1];
            float b2 = Vs[k * LDV + ct + 2];
            acc[0][0] += a0 * b0; acc[0][1] += a0 * b1; acc[0][2] += a0 * b2;
            acc[1][0] += a1 * b0; acc[1][1] += a1 * b1; acc[1][2] += a1 * b2;
        }
        const int obase = b * (TT * NE) + h * HS;
        #pragma unroll
        for (int i = 0; i < 2; ++i)
            #pragma unroll
            for (int j = 0; j < 3; ++j)
                g_ctx[obase + (rt + i) * NE + ct + j] = acc[i][j];
    }
}

// =====================================================================
// Kernel C: output projection  out = ctx @ Wproj + bproj
// =====================================================================
__global__ __launch_bounds__(256) void proj_kernel(
    const float* __restrict__ Wp,
    const float* __restrict__ bp,
    float* __restrict__ out)
{
    __shared__ __align__(16) float Ast[48][68];
    __shared__ __align__(16) float Bs [48][48];

    const int mt = blockIdx.x, nt = blockIdx.y;
    const int r0 = mt * 64, c0 = nt * 48;
    const int tid = threadIdx.x;
    const int tx = tid & 15, ty = tid >> 4;

    float acc[4][3] = {};

    for (int kc = 0; kc < NE; kc += 48) {
        for (int i = tid; i < 64 * 48; i += 256) {
            int r = i / 48, k = i % 48;
            Ast[k][r] = g_ctx[(r0 + r) * NE + kc + k];
        }
        for (int i = tid; i < 48 * 48; i += 256) {
            int k = i / 48, c = i % 48;
            Bs[k][c] = Wp[(kc + k) * NE + c0 + c];
        }
        __syncthreads();
        #pragma unroll 8
        for (int k = 0; k < 48; ++k) {
            float4 af = *reinterpret_cast<const float4*>(&Ast[k][ty * 4]);
            float a[4] = {af.x, af.y, af.z, af.w};
            float b[3] = {Bs[k][tx * 3 + 0], Bs[k][tx * 3 + 1], Bs[k][tx * 3 + 2]};
            #pragma unroll
            for (int i = 0; i < 4; ++i)
                #pragma unroll
                for (int j = 0; j < 3; ++j)
                    acc[i][j] += a[i] * b[j];
        }
        __syncthreads();
    }
    #pragma unroll
    for (int j = 0; j < 3; ++j) {
        float bias = bp[c0 + tx * 3 + j];
        #pragma unroll
        for (int i = 0; i < 4; ++i)
            out[(r0 + ty * 4 + i) * NE + c0 + tx * 3 + j] = acc[i][j] + bias;
    }
}

// =====================================================================
extern "C" void kernel_launch(void* const* d_in, const int* in_sizes, int n_in,
                              void* d_out, int out_size)
{
    const float* x   = (const float*)d_in[0];
    const float* Wq  = (const float*)d_in[1];
    const float* Wk  = (const float*)d_in[2];
    const float* Wv  = (const float*)d_in[3];
    const float* rel = (const float*)d_in[4];
    const float* Wp  = (const float*)d_in[5];
    const float* bp  = (const float*)d_in[6];
    float* out = (float*)d_out;

    // Not a stream op: executes immediately, capture-safe, idempotent.
    cudaFuncSetAttribute(attn_kernel,
                         cudaFuncAttributeMaxDynamicSharedMemorySize, ATTN_SMEM);

    dim3 gA(MTOT / 64, NE / 48, 3);
    qkv_kernel<<<gA, 256>>>(x, Wq, Wk, Wv);

    attn_kernel<<<BB * NH, 512, ATTN_SMEM>>>(rel);

    dim3 gC(MTOT / 64, NE / 48, 1);
    proj_kernel<<<gC, 256>>>(Wp, bp, out);
}

// round 4
// speedup vs baseline: 1.0845x; 1.0845x over previous
#include <cstdint>
#include <cuda_runtime.h>
#include <cuda_bf16.h>

#define NH   6
#define HS   24
#define NE   144
#define TT   128
#define BB   256
#define MTOT (BB*TT)        // 32768 tokens
#define LDA  152            // smem row stride (bf16 elems) for A/B tiles

// ---------------- device scratch (allocation-free) ----------------
__device__ float g_q[MTOT*NE];
__device__ float g_k[MTOT*NE];
__device__ float g_v[MTOT*NE];
__device__ float g_ctx[MTOT*NE];

// =====================================================================
// bf16-split tensor-core GEMM core: out[128 x 144] = in_tile @ W (+bias)
//   in  : [MTOT x 144] fp32 row-major, rows r0..r0+127
//   W   : [144 x 144]  fp32 row-major (k-major) -> transposed to [n][k] smem
//   3-term split: Ahi*Bhi + Alo*Bhi + Ahi*Blo  (~2^-16 effective precision)
// 256 threads = 8 warps: 4 along M (32 rows), 2 along N (72 cols).
// Each warp: 2 m16 tiles x 9 n8 tiles, K = 9 steps of 16.
// =====================================================================
#define GEMM_SMEM ((2*128*LDA + 2*144*LDA) * 2)   // 165376 B

__device__ __forceinline__ void mma_bf16(float c[4],
    uint32_t a0, uint32_t a1, uint32_t a2, uint32_t a3,
    uint32_t b0, uint32_t b1)
{
    asm volatile(
        "mma.sync.aligned.m16n8k16.row.col.f32.bf16.bf16.f32 "
        "{%0,%1,%2,%3}, {%4,%5,%6,%7}, {%8,%9}, {%0,%1,%2,%3};"
        : "+f"(c[0]), "+f"(c[1]), "+f"(c[2]), "+f"(c[3])
        : "r"(a0), "r"(a1), "r"(a2), "r"(a3), "r"(b0), "r"(b1));
}

__device__ __forceinline__ void gemm_core(
    const float* __restrict__ in, const float* __restrict__ W,
    float* __restrict__ out, const float* __restrict__ bias, int r0)
{
    extern __shared__ __align__(16) __nv_bfloat16 sm[];
    __nv_bfloat16* Ahi = sm;
    __nv_bfloat16* Alo = Ahi + 128 * LDA;
    __nv_bfloat16* Bhi = Alo + 128 * LDA;
    __nv_bfloat16* Blo = Bhi + 144 * LDA;

    const int tid = threadIdx.x;

    // load + split A tile (128 x 144)
    for (int i = tid; i < 128 * NE; i += 256) {
        int r = i / NE, c = i % NE;
        float v = in[(r0 + r) * NE + c];
        __nv_bfloat16 h = __float2bfloat16(v);
        Ahi[r * LDA + c] = h;
        Alo[r * LDA + c] = __float2bfloat16(v - __bfloat162float(h));
    }
    // load + split W transposed: W[k][n] -> B[n][k]
    for (int i = tid; i < NE * NE; i += 256) {
        int k = i / NE, n = i % NE;
        float v = W[i];
        __nv_bfloat16 h = __float2bfloat16(v);
        Bhi[n * LDA + k] = h;
        Blo[n * LDA + k] = __float2bfloat16(v - __bfloat162float(h));
    }
    __syncthreads();

    const int w    = tid >> 5, lane = tid & 31;
    const int g    = lane >> 2, t    = lane & 3;
    const int mrow = (w & 3) * 32;          // warp's M offset in tile
    const int ncol = (w >> 2) * 72;         // warp's N offset

    float acc[2][9][4];
    #pragma unroll
    for (int mt = 0; mt < 2; ++mt)
        #pragma unroll
        for (int nt = 0; nt < 9; ++nt)
            #pragma unroll
            for (int j = 0; j < 4; ++j) acc[mt][nt][j] = 0.f;

    const __nv_bfloat16* Ap3[3] = {Ahi, Alo, Ahi};
    const __nv_bfloat16* Bp3[3] = {Bhi, Bhi, Blo};

    #pragma unroll 1
    for (int p = 0; p < 3; ++p) {
        const __nv_bfloat16* Ap = Ap3[p];
        const __nv_bfloat16* Bp = Bp3[p];
        #pragma unroll
        for (int ks = 0; ks < 9; ++ks) {
            const int k0 = ks * 16;
            uint32_t a[2][4];
            #pragma unroll
            for (int mt = 0; mt < 2; ++mt) {
                const __nv_bfloat16* ab = Ap + (mrow + mt * 16 + g) * LDA + k0 + 2 * t;
                a[mt][0] = *(const uint32_t*)(ab);
                a[mt][1] = *(const uint32_t*)(ab + 8 * LDA);
                a[mt][2] = *(const uint32_t*)(ab + 8);
                a[mt][3] = *(const uint32_t*)(ab + 8 * LDA + 8);
            }
            #pragma unroll
            for (int nt = 0; nt < 9; ++nt) {
                const __nv_bfloat16* bb = Bp + (ncol + nt * 8 + g) * LDA + k0 + 2 * t;
                uint32_t b0 = *(const uint32_t*)(bb);
                uint32_t b1 = *(const uint32_t*)(bb + 8);
                mma_bf16(acc[0][nt], a[0][0], a[0][1], a[0][2], a[0][3], b0, b1);
                mma_bf16(acc[1][nt], a[1][0], a[1][1], a[1][2], a[1][3], b0, b1);
            }
        }
    }

    // writeout: c0=(g,2t) c1=(g,2t+1) c2=(g+8,2t) c3=(g+8,2t+1)
    #pragma unroll
    for (int mt = 0; mt < 2; ++mt) {
        #pragma unroll
        for (int nt = 0; nt < 9; ++nt) {
            int row = r0 + mrow + mt * 16 + g;
            int col = ncol + nt * 8 + 2 * t;
            float b0v = bias ? bias[col]     : 0.f;
            float b1v = bias ? bias[col + 1] : 0.f;
            out[row * NE + col]           = acc[mt][nt][0] + b0v;
            out[row * NE + col + 1]       = acc[mt][nt][1] + b1v;
            out[(row + 8) * NE + col]     = acc[mt][nt][2] + b0v;
            out[(row + 8) * NE + col + 1] = acc[mt][nt][3] + b1v;
        }
    }
}

// grid (256, 3): y picks q/k/v
__global__ __launch_bounds__(256) void qkv_mma_kernel(
    const float* __restrict__ x,
    const float* __restrict__ Wq,
    const float* __restrict__ Wk,
    const float* __restrict__ Wv)
{
    const int z = blockIdx.y;
    const float* W = (z == 0) ? Wq : ((z == 1) ? Wk : Wv);
    float* o       = (z == 0) ? g_q : ((z == 1) ? g_k : g_v);
    gemm_core(x, W, o, nullptr, blockIdx.x * 128);
}

__global__ __launch_bounds__(256) void proj_mma_kernel(
    const float* __restrict__ Wp,
    const float* __restrict__ bp,
    float* __restrict__ out)
{
    gemm_core(g_ctx, Wp, out, bp, blockIdx.x * 128);
}

// =====================================================================
// Kernel B: attention per (b,h). UNCHANGED from round-2 passing version.
// =====================================================================
#define LDT  132
#define LDV  25
#define LDSS 132
#define ATTN_SMEM ((3*24*LDT + 128*LDV + 128*LDSS) * 4)   // 118400 B

__global__ __launch_bounds__(512) void attn_kernel(const float* __restrict__ rel_table)
{
    extern __shared__ __align__(16) float smf[];
    float* Qt = smf;
    float* Kt = Qt + 24 * LDT;
    float* Rt = Kt + 24 * LDT;
    float* Vs = Rt + 24 * LDT;
    float* S  = Vs + 128 * LDV;

    const int bh = blockIdx.x;
    const int b = bh / NH, h = bh % NH;
    const int base = b * (TT * NE) + h * (TT * HS);
    const int tid = threadIdx.x;
    const float scale = 0.2041241452319315f;

    for (int i = tid; i < TT * HS; i += 512) {
        int t = i / HS, d = i % HS;
        Qt[d * LDT + t] = g_q[base + i];
        Kt[d * LDT + t] = g_k[base + i] * scale;
        Rt[d * LDT + t] = rel_table[(TT - 1) * HS + i];
        Vs[t * LDV + d] = g_v[base + i];
    }
    __syncthreads();

    const int tx = tid & 31, ty = tid >> 5;
    const int t0 = ty * 8, s0 = tx * 4;

    {   // S = Q @ K'^T
        float acc[8][4] = {};
        #pragma unroll
        for (int d = 0; d < 24; ++d) {
            float4 bv = *reinterpret_cast<const float4*>(&Kt[d * LDT + s0]);
            float4 a0 = *reinterpret_cast<const float4*>(&Qt[d * LDT + t0]);
            float4 a1 = *reinterpret_cast<const float4*>(&Qt[d * LDT + t0 + 4]);
            float av[8] = {a0.x, a0.y, a0.z, a0.w, a1.x, a1.y, a1.z, a1.w};
            #pragma unroll
            for (int i = 0; i < 8; ++i) {
                acc[i][0] += av[i] * bv.x;  acc[i][1] += av[i] * bv.y;
                acc[i][2] += av[i] * bv.z;  acc[i][3] += av[i] * bv.w;
            }
        }
        #pragma unroll
        for (int i = 0; i < 8; ++i)
            *reinterpret_cast<float4*>(&S[(t0 + i) * LDSS + s0]) =
                make_float4(acc[i][0], acc[i][1], acc[i][2], acc[i][3]);
    }
    __syncthreads();

    {   // rel term scatter-add
        float acc[8][4] = {};
        #pragma unroll
        for (int d = 0; d < 24; ++d) {
            float4 bv = *reinterpret_cast<const float4*>(&Rt[d * LDT + s0]);
            float4 a0 = *reinterpret_cast<const float4*>(&Qt[d * LDT + t0]);
            float4 a1 = *reinterpret_cast<const float4*>(&Qt[d * LDT + t0 + 4]);
            float av[8] = {a0.x, a0.y, a0.z, a0.w, a1.x, a1.y, a1.z, a1.w};
            #pragma unroll
            for (int i = 0; i < 8; ++i) {
                acc[i][0] += av[i] * bv.x;  acc[i][1] += av[i] * bv.y;
                acc[i][2] += av[i] * bv.z;  acc[i][3] += av[i] * bv.w;
            }
        }
        #pragma unroll
        for (int i = 0; i < 8; ++i) {
            int t = t0 + i;
            #pragma unroll
            for (int j = 0; j < 4; ++j) {
                int s = t - (s0 + j);
                if (s >= 0) S[t * LDSS + s] += acc[i][j];
            }
        }
    }
    __syncthreads();

    {   // softmax
        const int w = tid >> 5, lane = tid & 31;
        for (int r = 0; r < 8; ++r) {
            int t = w * 8 + r;
            float x0 = (lane      <= t) ? S[t * LDSS + lane     ] : -1e30f;
            float x1 = (lane + 32 <= t) ? S[t * LDSS + lane + 32] : -1e30f;
            float x2 = (lane + 64 <= t) ? S[t * LDSS + lane + 64] : -1e30f;
            float x3 = (lane + 96 <= t) ? S[t * LDSS + lane + 96] : -1e30f;
            float m = fmaxf(fmaxf(x0, x1), fmaxf(x2, x3));
            #pragma unroll
            for (int o = 16; o > 0; o >>= 1)
                m = fmaxf(m, __shfl_xor_sync(0xffffffffu, m, o));
            float e0 = (lane      <= t) ? __expf(x0 - m) : 0.f;
            float e1 = (lane + 32 <= t) ? __expf(x1 - m) : 0.f;
            float e2 = (lane + 64 <= t) ? __expf(x2 - m) : 0.f;
            float e3 = (lane + 96 <= t) ? __expf(x3 - m) : 0.f;
            float ssum = e0 + e1 + e2 + e3;
            #pragma unroll
            for (int o = 16; o > 0; o >>= 1)
                ssum += __shfl_xor_sync(0xffffffffu, ssum, o);
            float inv = 1.0f / ssum;
            S[t * LDSS + lane     ] = e0 * inv;
            S[t * LDSS + lane + 32] = e1 * inv;
            S[t * LDSS + lane + 64] = e2 * inv;
            S[t * LDSS + lane + 96] = e3 * inv;
        }
    }
    __syncthreads();

    {   // ctx = S @ V
        const int tx3 = tid & 7, ty3 = tid >> 3;
        const int rt = ty3 * 2, ct = tx3 * 3;
        float acc[2][3] = {};
        #pragma unroll 4
        for (int k = 0; k < TT; ++k) {
            float a0 = S[(rt    ) * LDSS + k];
            float a1 = S[(rt + 1) * LDSS + k];
            float b0 = Vs[k * LDV + ct    ];
            float b1 = Vs[k * LDV + ct + 1];
            float b2 = Vs[k * LDV + ct + 2];
            acc[0][0] += a0 * b0; acc[0][1] += a0 * b1; acc[0][2] += a0 * b2;
            acc[1][0] += a1 * b0; acc[1][1] += a1 * b1; acc[1][2] += a1 * b2;
        }
        const int obase = b * (TT * NE) + h * HS;
        #pragma unroll
        for (int i = 0; i < 2; ++i)
            #pragma unroll
            for (int j = 0; j < 3; ++j)
                g_ctx[obase + (rt + i) * NE + ct + j] = acc[i][j];
    }
}

// =====================================================================
extern "C" void kernel_launch(void* const* d_in, const int* in_sizes, int n_in,
                              void* d_out, int out_size)
{
    const float* x   = (const float*)d_in[0];
    const float* Wq  = (const float*)d_in[1];
    const float* Wk  = (const float*)d_in[2];
    const float* Wv  = (const float*)d_in[3];
    const float* rel = (const float*)d_in[4];
    const float* Wp  = (const float*)d_in[5];
    const float* bp  = (const float*)d_in[6];
    float* out = (float*)d_out;

    cudaFuncSetAttribute(qkv_mma_kernel,
                         cudaFuncAttributeMaxDynamicSharedMemorySize, GEMM_SMEM);
    cudaFuncSetAttribute(proj_mma_kernel,
                         cudaFuncAttributeMaxDynamicSharedMemorySize, GEMM_SMEM);
    cudaFuncSetAttribute(attn_kernel,
                         cudaFuncAttributeMaxDynamicSharedMemorySize, ATTN_SMEM);

    dim3 gQ(MTOT / 128, 3);
    qkv_mma_kernel<<<gQ, 256, GEMM_SMEM>>>(x, Wq, Wk, Wv);

    attn_kernel<<<BB * NH, 512, ATTN_SMEM>>>(rel);

    proj_mma_kernel<<<MTOT / 128, 256, GEMM_SMEM>>>(Wp, bp, out);
}

// round 6
// speedup vs baseline: 1.6136x; 1.4879x over previous
#include <cstdint>
#include <cuda_runtime.h>
#include <cuda_bf16.h>

#define NH   6
#define HS   24
#define NE   144
#define TT   128
#define BB   256
#define MTOT (BB*TT)        // 32768 tokens

typedef __nv_bfloat16 bf16;

// ---------------- device scratch (allocation-free, bf16 hi/lo pairs) --------
__device__ bf16 g_xhi[MTOT*NE], g_xlo[MTOT*NE];
__device__ bf16 g_qhi[MTOT*NE], g_qlo[MTOT*NE];
__device__ bf16 g_khi[MTOT*NE], g_klo[MTOT*NE];   // pre-scaled by 1/sqrt(hs)
__device__ bf16 g_vhi[MTOT*NE], g_vlo[MTOT*NE];
__device__ bf16 g_chi[MTOT*NE], g_clo[MTOT*NE];   // ctx, split
__device__ bf16 g_wthi[4*NE*NE], g_wtlo[4*NE*NE]; // W^T [n][k], q,k,v,proj
__device__ bf16 g_rhi[255*HS],   g_rlo[255*HS];   // rel_table split

// ---------------- helpers ----------------
__device__ __forceinline__ void mma_bf16(float c[4],
    uint32_t a0, uint32_t a1, uint32_t a2, uint32_t a3,
    uint32_t b0, uint32_t b1)
{
    asm volatile(
        "mma.sync.aligned.m16n8k16.row.col.f32.bf16.bf16.f32 "
        "{%0,%1,%2,%3}, {%4,%5,%6,%7}, {%8,%9}, {%0,%1,%2,%3};"
        : "+f"(c[0]), "+f"(c[1]), "+f"(c[2]), "+f"(c[3])
        : "r"(a0), "r"(a1), "r"(a2), "r"(a3), "r"(b0), "r"(b1));
}

// pack two floats (col2t, col2t+1) into bf16x2 hi-part and residual lo-part
__device__ __forceinline__ void split2(float v0, float v1, uint32_t& hi, uint32_t& lo)
{
    bf16 h0 = __float2bfloat16(v0), h1 = __float2bfloat16(v1);
    float r0 = v0 - __bfloat162float(h0), r1 = v1 - __bfloat162float(h1);
    hi = ((uint32_t)__bfloat16_as_ushort(h1) << 16) | __bfloat16_as_ushort(h0);
    lo = ((uint32_t)__bfloat16_as_ushort(__float2bfloat16(r1)) << 16)
       |  (uint32_t)__bfloat16_as_ushort(__float2bfloat16(r0));
}

// =====================================================================
// Setup kernels (run every launch; cheap, memory-bound)
// =====================================================================
__global__ __launch_bounds__(256) void split_x_kernel(const float* __restrict__ x)
{
    int i0 = (blockIdx.x * 256 + threadIdx.x) * 8;
    if (i0 >= MTOT * NE) return;
    bf16 hi[8], lo[8];
    #pragma unroll
    for (int j = 0; j < 8; ++j) {
        float v = x[i0 + j];
        hi[j] = __float2bfloat16(v);
        lo[j] = __float2bfloat16(v - __bfloat162float(hi[j]));
    }
    *(uint4*)&g_xhi[i0] = *(uint4*)hi;
    *(uint4*)&g_xlo[i0] = *(uint4*)lo;
}

__global__ __launch_bounds__(256) void split_wr_kernel(
    const float* __restrict__ Wq, const float* __restrict__ Wk,
    const float* __restrict__ Wv, const float* __restrict__ Wp,
    const float* __restrict__ rel)
{
    int m = blockIdx.y;
    int i = blockIdx.x * 256 + threadIdx.x;
    if (m < 4) {                      // transpose + split a 144x144 weight
        if (i >= NE * NE) return;
        const float* src = (m == 0) ? Wq : (m == 1) ? Wk : (m == 2) ? Wv : Wp;
        int k = i / NE, n = i - k * NE;
        float v = src[i];
        bf16 h = __float2bfloat16(v);
        g_wthi[m * NE * NE + n * NE + k] = h;
        g_wtlo[m * NE * NE + n * NE + k] = __float2bfloat16(v - __bfloat162float(h));
    } else {                          // rel_table split
        if (i >= 255 * HS) return;
        float v = rel[i];
        bf16 h = __float2bfloat16(v);
        g_rhi[i] = h;
        g_rlo[i] = __float2bfloat16(v - __bfloat162float(h));
    }
}

// =====================================================================
// GEMM v2 core: out[128 x 144] = A @ W, K-chunked (3 x 48), bf16 3-term split
// smem 60928 B -> 2 CTAs/SM.  8 warps: 4 along M (32 rows), 2 along N (72).
// =====================================================================
#define LDS2 56
#define GSMEM ((128*LDS2 + 128*LDS2 + 144*LDS2 + 144*LDS2) * 2)   // 60928

__device__ __forceinline__ void gemm2_core(
    const bf16* __restrict__ Ahig, const bf16* __restrict__ Alog,
    const bf16* __restrict__ Wthi, const bf16* __restrict__ Wtlo,
    int r0, float oscale, bf16* ohi, bf16* olo,
    float* ofp, const float* __restrict__ bias)
{
    extern __shared__ __align__(16) char smc[];
    bf16* As_hi = (bf16*)smc;                 // [128][56]
    bf16* As_lo = As_hi + 128 * LDS2;
    bf16* Bs_hi = As_lo + 128 * LDS2;         // [144][56]
    bf16* Bs_lo = Bs_hi + 144 * LDS2;

    const int tid = threadIdx.x;
    const int w = tid >> 5, lane = tid & 31, g = lane >> 2, t = lane & 3;
    const int mrow = (w & 3) * 32, ncol = (w >> 2) * 72;

    float acc[2][9][4];
    #pragma unroll
    for (int mt = 0; mt < 2; ++mt)
        #pragma unroll
        for (int nt = 0; nt < 9; ++nt)
            #pragma unroll
            for (int j = 0; j < 4; ++j) acc[mt][nt][j] = 0.f;

    #pragma unroll 1
    for (int kc = 0; kc < NE; kc += 48) {
        for (int i = tid; i < 128 * 6; i += 256) {
            int r = i / 6, j = i - r * 6;
            *(uint4*)&As_hi[r * LDS2 + j * 8] = *(const uint4*)&Ahig[(r0 + r) * NE + kc + j * 8];
            *(uint4*)&As_lo[r * LDS2 + j * 8] = *(const uint4*)&Alog[(r0 + r) * NE + kc + j * 8];
        }
        for (int i = tid; i < 144 * 6; i += 256) {
            int r = i / 6, j = i - r * 6;
            *(uint4*)&Bs_hi[r * LDS2 + j * 8] = *(const uint4*)&Wthi[r * NE + kc + j * 8];
            *(uint4*)&Bs_lo[r * LDS2 + j * 8] = *(const uint4*)&Wtlo[r * NE + kc + j * 8];
        }
        __syncthreads();

        #pragma unroll 1
        for (int p = 0; p < 3; ++p) {
            const bf16* Ap = (p == 1) ? As_lo : As_hi;
            const bf16* Bp = (p == 2) ? Bs_lo : Bs_hi;
            #pragma unroll
            for (int ks = 0; ks < 3; ++ks) {
                const int k0 = ks * 16;
                uint32_t a[2][4];
                #pragma unroll
                for (int mt = 0; mt < 2; ++mt) {
                    const bf16* ab = Ap + (mrow + mt * 16 + g) * LDS2 + k0 + 2 * t;
                    a[mt][0] = *(const uint32_t*)(ab);
                    a[mt][1] = *(const uint32_t*)(ab + 8 * LDS2);
                    a[mt][2] = *(const uint32_t*)(ab + 8);
                    a[mt][3] = *(const uint32_t*)(ab + 8 * LDS2 + 8);
                }
                #pragma unroll
                for (int nt = 0; nt < 9; ++nt) {
                    const bf16* bb = Bp + (ncol + nt * 8 + g) * LDS2 + k0 + 2 * t;
                    uint32_t b0 = *(const uint32_t*)(bb);
                    uint32_t b1 = *(const uint32_t*)(bb + 8);
                    mma_bf16(acc[0][nt], a[0][0], a[0][1], a[0][2], a[0][3], b0, b1);
                    mma_bf16(acc[1][nt], a[1][0], a[1][1], a[1][2], a[1][3], b0, b1);
                }
            }
        }
        __syncthreads();
    }

    #pragma unroll
    for (int mt = 0; mt < 2; ++mt) {
        #pragma unroll
        for (int nt = 0; nt < 9; ++nt) {
            int row = r0 + mrow + mt * 16 + g;
            int col = ncol + nt * 8 + 2 * t;
            if (ofp) {
                float b0v = bias[col], b1v = bias[col + 1];
                ofp[row * NE + col]           = acc[mt][nt][0] + b0v;
                ofp[row * NE + col + 1]       = acc[mt][nt][1] + b1v;
                ofp[(row + 8) * NE + col]     = acc[mt][nt][2] + b0v;
                ofp[(row + 8) * NE + col + 1] = acc[mt][nt][3] + b1v;
            } else {
                uint32_t h, l;
                split2(acc[mt][nt][0] * oscale, acc[mt][nt][1] * oscale, h, l);
                *(uint32_t*)&ohi[row * NE + col] = h;
                *(uint32_t*)&olo[row * NE + col] = l;
                split2(acc[mt][nt][2] * oscale, acc[mt][nt][3] * oscale, h, l);
                *(uint32_t*)&ohi[(row + 8) * NE + col] = h;
                *(uint32_t*)&olo[(row + 8) * NE + col] = l;
            }
        }
    }
}

__global__ __launch_bounds__(256, 2) void qkv2_kernel()
{
    const int z = blockIdx.y;
    const bf16* wh = g_wthi + z * NE * NE;
    const bf16* wl = g_wtlo + z * NE * NE;
    bf16 *oh, *ol;
    float sc = 1.f;
    if (z == 0)      { oh = g_qhi; ol = g_qlo; }
    else if (z == 1) { oh = g_khi; ol = g_klo; sc = 0.2041241452319315f; }
    else             { oh = g_vhi; ol = g_vlo; }
    gemm2_core(g_xhi, g_xlo, wh, wl, blockIdx.x * 128, sc, oh, ol, nullptr, nullptr);
}

__global__ __launch_bounds__(256, 2) void proj2_kernel(
    const float* __restrict__ bias, float* __restrict__ out)
{
    gemm2_core(g_chi, g_clo, g_wthi + 3 * NE * NE, g_wtlo + 3 * NE * NE,
               blockIdx.x * 128, 1.f, nullptr, nullptr, out, bias);
}

// =====================================================================
// Attention v2: tensor-core S/P/ctx GEMMs + verified fp32 softmax/scatter.
// 256 threads (8 warps), 1536 blocks.
// smem: S fp32 [128][132] | Q/K/R hi+lo bf16 [128][40] | Vt hi+lo [24][136]
// =====================================================================
#define ALD   40      // Q/K/R row stride (bf16), k padded 24->32, pad zeroed
#define VLD   136     // Vt row stride (bf16)
#define SLD   132     // S row stride (fp32)
#define ASMEM (128*SLD*4 + 6*128*ALD*2 + 2*24*VLD*2)   // 142080 B

__global__ __launch_bounds__(256, 1) void attn2_kernel()
{
    extern __shared__ __align__(16) char smc[];
    float* S   = (float*)smc;                                  // 67584 B
    bf16* Qhi  = (bf16*)(smc + 128 * SLD * 4);
    bf16* Qlo  = Qhi + 128 * ALD;
    bf16* Khi  = Qlo + 128 * ALD;
    bf16* Klo  = Khi + 128 * ALD;
    bf16* Rhi  = Klo + 128 * ALD;
    bf16* Rlo  = Rhi + 128 * ALD;
    bf16* Vthi = Rlo + 128 * ALD;
    bf16* Vtlo = Vthi + 24 * VLD;

    const int bh = blockIdx.x;
    const int b = bh / NH, h = bh % NH;
    const int base = b * (TT * NE) + h * (TT * HS);   // contiguous head chunk
    const int tid = threadIdx.x;

    // ---- preamble: copy pre-split bf16 Q,K,R; transpose V ----
    {
        const int row = tid >> 1;
        const int half = (tid & 1) * 12;
        const int src = base + row * HS + half;
        const int dst = row * ALD + half;
        #pragma unroll
        for (int j = 0; j < 12; j += 2) {
            *(uint32_t*)&Qhi[dst + j] = *(const uint32_t*)&g_qhi[src + j];
            *(uint32_t*)&Qlo[dst + j] = *(const uint32_t*)&g_qlo[src + j];
            *(uint32_t*)&Khi[dst + j] = *(const uint32_t*)&g_khi[src + j];
            *(uint32_t*)&Klo[dst + j] = *(const uint32_t*)&g_klo[src + j];
        }
        const int rsrc = (127 + row) * HS + half;
        #pragma unroll
        for (int j = 0; j < 12; j += 2) {
            *(uint32_t*)&Rhi[dst + j] = *(const uint32_t*)&g_rhi[rsrc + j];
            *(uint32_t*)&Rlo[dst + j] = *(const uint32_t*)&g_rlo[rsrc + j];
        }
        #pragma unroll
        for (int j = 0; j < 12; ++j) {
            Vthi[(half + j) * VLD + row] = g_vhi[src + j];
            Vtlo[(half + j) * VLD + row] = g_vlo[src + j];
        }
        if (tid < 128) {   // zero k-pad cols 24..31 (read by ks=1 step)
            uint4 z4 = make_uint4(0, 0, 0, 0);
            *(uint4*)&Qhi[tid * ALD + 24] = z4;  *(uint4*)&Qlo[tid * ALD + 24] = z4;
            *(uint4*)&Khi[tid * ALD + 24] = z4;  *(uint4*)&Klo[tid * ALD + 24] = z4;
            *(uint4*)&Rhi[tid * ALD + 24] = z4;  *(uint4*)&Rlo[tid * ALD + 24] = z4;
        }
    }
    __syncthreads();

    const int w = tid >> 5, lane = tid & 31, g = lane >> 2, t = lane & 3;
    const int wm = w & 1, wn = w >> 1;     // 2 along M x 4 along N

    // ---- stage 1: S = Q @ K'^T  (K pre-scaled) ----
    {
        float acc[4][4][4];
        #pragma unroll
        for (int mt = 0; mt < 4; ++mt)
            #pragma unroll
            for (int nt = 0; nt < 4; ++nt)
                #pragma unroll
                for (int j = 0; j < 4; ++j) acc[mt][nt][j] = 0.f;
        #pragma unroll 1
        for (int p = 0; p < 3; ++p) {
            const bf16* Ap = (p == 1) ? Qlo : Qhi;
            const bf16* Bp = (p == 2) ? Klo : Khi;
            #pragma unroll
            for (int ks = 0; ks < 2; ++ks) {
                const int k0 = ks * 16;
                uint32_t a[4][4];
                #pragma unroll
                for (int mt = 0; mt < 4; ++mt) {
                    const bf16* ab = Ap + (wm * 64 + mt * 16 + g) * ALD + k0 + 2 * t;
                    a[mt][0] = *(const uint32_t*)(ab);
                    a[mt][1] = *(const uint32_t*)(ab + 8 * ALD);
                    a[mt][2] = *(const uint32_t*)(ab + 8);
                    a[mt][3] = *(const uint32_t*)(ab + 8 * ALD + 8);
                }
                #pragma unroll
                for (int nt = 0; nt < 4; ++nt) {
                    const bf16* bb = Bp + (wn * 32 + nt * 8 + g) * ALD + k0 + 2 * t;
                    uint32_t b0 = *(const uint32_t*)(bb);
                    uint32_t b1 = *(const uint32_t*)(bb + 8);
                    #pragma unroll
                    for (int mt = 0; mt < 4; ++mt)
                        mma_bf16(acc[mt][nt], a[mt][0], a[mt][1], a[mt][2], a[mt][3], b0, b1);
                }
            }
        }
        #pragma unroll
        for (int mt = 0; mt < 4; ++mt)
            #pragma unroll
            for (int nt = 0; nt < 4; ++nt) {
                int row = wm * 64 + mt * 16 + g;
                int col = wn * 32 + nt * 8 + 2 * t;
                *(float2*)&S[row * SLD + col]       = make_float2(acc[mt][nt][0], acc[mt][nt][1]);
                *(float2*)&S[(row + 8) * SLD + col] = make_float2(acc[mt][nt][2], acc[mt][nt][3]);
            }
    }
    __syncthreads();

    // ---- stage 2: P = Q @ R^T, scatter S[t][t-j] += P[t][j] (unique (t,s)) ----
    {
        float acc[4][4][4];
        #pragma unroll
        for (int mt = 0; mt < 4; ++mt)
            #pragma unroll
            for (int nt = 0; nt < 4; ++nt)
                #pragma unroll
                for (int j = 0; j < 4; ++j) acc[mt][nt][j] = 0.f;
        #pragma unroll 1
        for (int p = 0; p < 3; ++p) {
            const bf16* Ap = (p == 1) ? Qlo : Qhi;
            const bf16* Bp = (p == 2) ? Rlo : Rhi;
            #pragma unroll
            for (int ks = 0; ks < 2; ++ks) {
                const int k0 = ks * 16;
                uint32_t a[4][4];
                #pragma unroll
                for (int mt = 0; mt < 4; ++mt) {
                    const bf16* ab = Ap + (wm * 64 + mt * 16 + g) * ALD + k0 + 2 * t;
                    a[mt][0] = *(const uint32_t*)(ab);
                    a[mt][1] = *(const uint32_t*)(ab + 8 * ALD);
                    a[mt][2] = *(const uint32_t*)(ab + 8);
                    a[mt][3] = *(const uint32_t*)(ab + 8 * ALD + 8);
                }
                #pragma unroll
                for (int nt = 0; nt < 4; ++nt) {
                    const bf16* bb = Bp + (wn * 32 + nt * 8 + g) * ALD + k0 + 2 * t;
                    uint32_t b0 = *(const uint32_t*)(bb);
                    uint32_t b1 = *(const uint32_t*)(bb + 8);
                    #pragma unroll
                    for (int mt = 0; mt < 4; ++mt)
                        mma_bf16(acc[mt][nt], a[mt][0], a[mt][1], a[mt][2], a[mt][3], b0, b1);
                }
            }
        }
        #pragma unroll
        for (int mt = 0; mt < 4; ++mt)
            #pragma unroll
            for (int nt = 0; nt < 4; ++nt) {
                int tr = wm * 64 + mt * 16 + g;
                int j0 = wn * 32 + nt * 8 + 2 * t;
                int s;
                s = tr - j0;           if (s >= 0) S[tr * SLD + s]       += acc[mt][nt][0];
                s = tr - (j0 + 1);     if (s >= 0) S[tr * SLD + s]       += acc[mt][nt][1];
                s = (tr + 8) - j0;     if (s >= 0) S[(tr + 8) * SLD + s] += acc[mt][nt][2];
                s = (tr + 8) - (j0+1); if (s >= 0) S[(tr + 8) * SLD + s] += acc[mt][nt][3];
            }
    }
    __syncthreads();

    // ---- softmax: 8 warps x 16 rows, causal mask, masked -> 0 ----
    {
        for (int r = 0; r < 16; ++r) {
            int trow = w * 16 + r;
            float x0 = (lane      <= trow) ? S[trow * SLD + lane     ] : -1e30f;
            float x1 = (lane + 32 <= trow) ? S[trow * SLD + lane + 32] : -1e30f;
            float x2 = (lane + 64 <= trow) ? S[trow * SLD + lane + 64] : -1e30f;
            float x3 = (lane + 96 <= trow) ? S[trow * SLD + lane + 96] : -1e30f;
            float m = fmaxf(fmaxf(x0, x1), fmaxf(x2, x3));
            #pragma unroll
            for (int o = 16; o > 0; o >>= 1)
                m = fmaxf(m, __shfl_xor_sync(0xffffffffu, m, o));
            float e0 = (lane      <= trow) ? __expf(x0 - m) : 0.f;
            float e1 = (lane + 32 <= trow) ? __expf(x1 - m) : 0.f;
            float e2 = (lane + 64 <= trow) ? __expf(x2 - m) : 0.f;
            float e3 = (lane + 96 <= trow) ? __expf(x3 - m) : 0.f;
            float ssum = e0 + e1 + e2 + e3;
            #pragma unroll
            for (int o = 16; o > 0; o >>= 1)
                ssum += __shfl_xor_sync(0xffffffffu, ssum, o);
            float inv = 1.0f / ssum;
            S[trow * SLD + lane     ] = e0 * inv;
            S[trow * SLD + lane + 32] = e1 * inv;
            S[trow * SLD + lane + 64] = e2 * inv;
            S[trow * SLD + lane + 96] = e3 * inv;
        }
    }
    __syncthreads();

    // ---- stage 3: ctx = S @ V  (A = S split on the fly, B = Vt hi/lo) ----
    {
        float acc[3][4];
        #pragma unroll
        for (int nt = 0; nt < 3; ++nt)
            #pragma unroll
            for (int j = 0; j < 4; ++j) acc[nt][j] = 0.f;

        #pragma unroll
        for (int ks = 0; ks < 8; ++ks) {
            const int k0 = ks * 16;
            float2 p0 = *(const float2*)&S[(w * 16 + g)     * SLD + k0 + 2 * t];
            float2 p1 = *(const float2*)&S[(w * 16 + g + 8) * SLD + k0 + 2 * t];
            float2 p2 = *(const float2*)&S[(w * 16 + g)     * SLD + k0 + 2 * t + 8];
            float2 p3 = *(const float2*)&S[(w * 16 + g + 8) * SLD + k0 + 2 * t + 8];
            uint32_t ah0, al0, ah1, al1, ah2, al2, ah3, al3;
            split2(p0.x, p0.y, ah0, al0);
            split2(p1.x, p1.y, ah1, al1);
            split2(p2.x, p2.y, ah2, al2);
            split2(p3.x, p3.y, ah3, al3);
            #pragma unroll
            for (int nt = 0; nt < 3; ++nt) {
                const bf16* bh = Vthi + (nt * 8 + g) * VLD + k0 + 2 * t;
                const bf16* bl = Vtlo + (nt * 8 + g) * VLD + k0 + 2 * t;
                uint32_t bh0 = *(const uint32_t*)(bh);
                uint32_t bh1 = *(const uint32_t*)(bh + 8);
                uint32_t bl0 = *(const uint32_t*)(bl);
                uint32_t bl1 = *(const uint32_t*)(bl + 8);
                mma_bf16(acc[nt], ah0, ah1, ah2, ah3, bh0, bh1);
                mma_bf16(acc[nt], al0, al1, al2, al3, bh0, bh1);
                mma_bf16(acc[nt], ah0, ah1, ah2, ah3, bl0, bl1);
            }
        }

        // writeout: split to g_chi/g_clo at [b*128+row][h*24+col]
        #pragma unroll
        for (int nt = 0; nt < 3; ++nt) {
            int row = w * 16 + g;
            int col = nt * 8 + 2 * t;
            int idx = b * (TT * NE) + row * NE + h * HS + col;
            uint32_t hp, lp;
            split2(acc[nt][0], acc[nt][1], hp, lp);
            *(uint32_t*)&g_chi[idx] = hp;
            *(uint32_t*)&g_clo[idx] = lp;
            split2(acc[nt][2], acc[nt][3], hp, lp);
            *(uint32_t*)&g_chi[idx + 8 * NE] = hp;
            *(uint32_t*)&g_clo[idx + 8 * NE] = lp;
        }
    }
}

// =====================================================================
extern "C" void kernel_launch(void* const* d_in, const int* in_sizes, int n_in,
                              void* d_out, int out_size)
{
    const float* x   = (const float*)d_in[0];
    const float* Wq  = (const float*)d_in[1];
    const float* Wk  = (const float*)d_in[2];
    const float* Wv  = (const float*)d_in[3];
    const float* rel = (const float*)d_in[4];
    const float* Wp  = (const float*)d_in[5];
    const float* bp  = (const float*)d_in[6];
    float* out = (float*)d_out;

    cudaFuncSetAttribute(qkv2_kernel,
                         cudaFuncAttributeMaxDynamicSharedMemorySize, GSMEM);
    cudaFuncSetAttribute(proj2_kernel,
                         cudaFuncAttributeMaxDynamicSharedMemorySize, GSMEM);
    cudaFuncSetAttribute(attn2_kernel,
                         cudaFuncAttributeMaxDynamicSharedMemorySize, ASMEM);

    split_x_kernel<<<(MTOT * NE) / (256 * 8), 256>>>(x);
    split_wr_kernel<<<dim3(81, 5), 256>>>(Wq, Wk, Wv, Wp, rel);

    dim3 gQ(MTOT / 128, 3);
    qkv2_kernel<<<gQ, 256, GSMEM>>>();

    attn2_kernel<<<BB * NH, 256, ASMEM>>>();

    proj2_kernel<<<MTOT / 128, 256, GSMEM>>>(bp, out);
}

// round 8
// speedup vs baseline: 1.7935x; 1.1115x over previous
#include <cstdint>
#include <cuda_runtime.h>
#include <cuda_bf16.h>

#define NH   6
#define HS   24
#define NE   144
#define TT   128
#define BB   256
#define MTOT (BB*TT)        // 32768 tokens

typedef __nv_bfloat16 bf16;

// ---------------- device scratch (allocation-free, bf16 hi/lo pairs) --------
__device__ bf16 g_xhi[MTOT*NE], g_xlo[MTOT*NE];
__device__ bf16 g_qhi[MTOT*NE], g_qlo[MTOT*NE];
__device__ bf16 g_khi[MTOT*NE], g_klo[MTOT*NE];   // pre-scaled by 1/sqrt(hs)
__device__ bf16 g_vhi[MTOT*NE], g_vlo[MTOT*NE];
__device__ bf16 g_chi[MTOT*NE], g_clo[MTOT*NE];   // ctx, split
__device__ bf16 g_wthi[4*NE*NE], g_wtlo[4*NE*NE]; // W^T [n][k], q,k,v,proj
__device__ bf16 g_rhi[255*HS],   g_rlo[255*HS];   // rel_table split

// ---------------- helpers ----------------
__device__ __forceinline__ void mma_bf16(float c[4],
    uint32_t a0, uint32_t a1, uint32_t a2, uint32_t a3,
    uint32_t b0, uint32_t b1)
{
    asm volatile(
        "mma.sync.aligned.m16n8k16.row.col.f32.bf16.bf16.f32 "
        "{%0,%1,%2,%3}, {%4,%5,%6,%7}, {%8,%9}, {%0,%1,%2,%3};"
        : "+f"(c[0]), "+f"(c[1]), "+f"(c[2]), "+f"(c[3])
        : "r"(a0), "r"(a1), "r"(a2), "r"(a3), "r"(b0), "r"(b1));
}

__device__ __forceinline__ void split2(float v0, float v1, uint32_t& hi, uint32_t& lo)
{
    bf16 h0 = __float2bfloat16(v0), h1 = __float2bfloat16(v1);
    float r0 = v0 - __bfloat162float(h0), r1 = v1 - __bfloat162float(h1);
    hi = ((uint32_t)__bfloat16_as_ushort(h1) << 16) | __bfloat16_as_ushort(h0);
    lo = ((uint32_t)__bfloat16_as_ushort(__float2bfloat16(r1)) << 16)
       |  (uint32_t)__bfloat16_as_ushort(__float2bfloat16(r0));
}

// =====================================================================
// Setup kernels
// =====================================================================
__global__ __launch_bounds__(256) void split_x_kernel(const float* __restrict__ x)
{
    int i0 = (blockIdx.x * 256 + threadIdx.x) * 8;
    if (i0 >= MTOT * NE) return;
    bf16 hi[8], lo[8];
    #pragma unroll
    for (int j = 0; j < 8; ++j) {
        float v = x[i0 + j];
        hi[j] = __float2bfloat16(v);
        lo[j] = __float2bfloat16(v - __bfloat162float(hi[j]));
    }
    *(uint4*)&g_xhi[i0] = *(uint4*)hi;
    *(uint4*)&g_xlo[i0] = *(uint4*)lo;
}

__global__ __launch_bounds__(256) void split_wr_kernel(
    const float* __restrict__ Wq, const float* __restrict__ Wk,
    const float* __restrict__ Wv, const float* __restrict__ Wp,
    const float* __restrict__ rel)
{
    int m = blockIdx.y;
    int i = blockIdx.x * 256 + threadIdx.x;
    if (m < 4) {
        if (i >= NE * NE) return;
        const float* src = (m == 0) ? Wq : (m == 1) ? Wk : (m == 2) ? Wv : Wp;
        int k = i / NE, n = i - k * NE;
        float v = src[i];
        bf16 h = __float2bfloat16(v);
        g_wthi[m * NE * NE + n * NE + k] = h;
        g_wtlo[m * NE * NE + n * NE + k] = __float2bfloat16(v - __bfloat162float(h));
    } else {
        if (i >= 255 * HS) return;
        float v = rel[i];
        bf16 h = __float2bfloat16(v);
        g_rhi[i] = h;
        g_rlo[i] = __float2bfloat16(v - __bfloat162float(h));
    }
}

// =====================================================================
// GEMM v2 core (unchanged, validated): out[128x144] = A @ W, 2 CTAs/SM
// =====================================================================
#define LDS2 56
#define GSMEM ((128*LDS2 + 128*LDS2 + 144*LDS2 + 144*LDS2) * 2)   // 60928

__device__ __forceinline__ void gemm2_core(
    const bf16* __restrict__ Ahig, const bf16* __restrict__ Alog,
    const bf16* __restrict__ Wthi, const bf16* __restrict__ Wtlo,
    int r0, float oscale, bf16* ohi, bf16* olo,
    float* ofp, const float* __restrict__ bias)
{
    extern __shared__ __align__(16) char smc[];
    bf16* As_hi = (bf16*)smc;
    bf16* As_lo = As_hi + 128 * LDS2;
    bf16* Bs_hi = As_lo + 128 * LDS2;
    bf16* Bs_lo = Bs_hi + 144 * LDS2;

    const int tid = threadIdx.x;
    const int w = tid >> 5, lane = tid & 31, g = lane >> 2, t = lane & 3;
    const int mrow = (w & 3) * 32, ncol = (w >> 2) * 72;

    float acc[2][9][4];
    #pragma unroll
    for (int mt = 0; mt < 2; ++mt)
        #pragma unroll
        for (int nt = 0; nt < 9; ++nt)
            #pragma unroll
            for (int j = 0; j < 4; ++j) acc[mt][nt][j] = 0.f;

    #pragma unroll 1
    for (int kc = 0; kc < NE; kc += 48) {
        for (int i = tid; i < 128 * 6; i += 256) {
            int r = i / 6, j = i - r * 6;
            *(uint4*)&As_hi[r * LDS2 + j * 8] = *(const uint4*)&Ahig[(r0 + r) * NE + kc + j * 8];
            *(uint4*)&As_lo[r * LDS2 + j * 8] = *(const uint4*)&Alog[(r0 + r) * NE + kc + j * 8];
        }
        for (int i = tid; i < 144 * 6; i += 256) {
            int r = i / 6, j = i - r * 6;
            *(uint4*)&Bs_hi[r * LDS2 + j * 8] = *(const uint4*)&Wthi[r * NE + kc + j * 8];
            *(uint4*)&Bs_lo[r * LDS2 + j * 8] = *(const uint4*)&Wtlo[r * NE + kc + j * 8];
        }
        __syncthreads();

        #pragma unroll 1
        for (int p = 0; p < 3; ++p) {
            const bf16* Ap = (p == 1) ? As_lo : As_hi;
            const bf16* Bp = (p == 2) ? Bs_lo : Bs_hi;
            #pragma unroll
            for (int ks = 0; ks < 3; ++ks) {
                const int k0 = ks * 16;
                uint32_t a[2][4];
                #pragma unroll
                for (int mt = 0; mt < 2; ++mt) {
                    const bf16* ab = Ap + (mrow + mt * 16 + g) * LDS2 + k0 + 2 * t;
                    a[mt][0] = *(const uint32_t*)(ab);
                    a[mt][1] = *(const uint32_t*)(ab + 8 * LDS2);
                    a[mt][2] = *(const uint32_t*)(ab + 8);
                    a[mt][3] = *(const uint32_t*)(ab + 8 * LDS2 + 8);
                }
                #pragma unroll
                for (int nt = 0; nt < 9; ++nt) {
                    const bf16* bb = Bp + (ncol + nt * 8 + g) * LDS2 + k0 + 2 * t;
                    uint32_t b0 = *(const uint32_t*)(bb);
                    uint32_t b1 = *(const uint32_t*)(bb + 8);
                    mma_bf16(acc[0][nt], a[0][0], a[0][1], a[0][2], a[0][3], b0, b1);
                    mma_bf16(acc[1][nt], a[1][0], a[1][1], a[1][2], a[1][3], b0, b1);
                }
            }
        }
        __syncthreads();
    }

    #pragma unroll
    for (int mt = 0; mt < 2; ++mt) {
        #pragma unroll
        for (int nt = 0; nt < 9; ++nt) {
            int row = r0 + mrow + mt * 16 + g;
            int col = ncol + nt * 8 + 2 * t;
            if (ofp) {
                float b0v = bias[col], b1v = bias[col + 1];
                ofp[row * NE + col]           = acc[mt][nt][0] + b0v;
                ofp[row * NE + col + 1]       = acc[mt][nt][1] + b1v;
                ofp[(row + 8) * NE + col]     = acc[mt][nt][2] + b0v;
                ofp[(row + 8) * NE + col + 1] = acc[mt][nt][3] + b1v;
            } else {
                uint32_t h, l;
                split2(acc[mt][nt][0] * oscale, acc[mt][nt][1] * oscale, h, l);
                *(uint32_t*)&ohi[row * NE + col] = h;
                *(uint32_t*)&olo[row * NE + col] = l;
                split2(acc[mt][nt][2] * oscale, acc[mt][nt][3] * oscale, h, l);
                *(uint32_t*)&ohi[(row + 8) * NE + col] = h;
                *(uint32_t*)&olo[(row + 8) * NE + col] = l;
            }
        }
    }
}

__global__ __launch_bounds__(256, 2) void qkv2_kernel()
{
    const int z = blockIdx.y;
    const bf16* wh = g_wthi + z * NE * NE;
    const bf16* wl = g_wtlo + z * NE * NE;
    bf16 *oh, *ol;
    float sc = 1.f;
    if (z == 0)      { oh = g_qhi; ol = g_qlo; }
    else if (z == 1) { oh = g_khi; ol = g_klo; sc = 0.2041241452319315f; }
    else             { oh = g_vhi; ol = g_vlo; }
    gemm2_core(g_xhi, g_xlo, wh, wl, blockIdx.x * 128, sc, oh, ol, nullptr, nullptr);
}

__global__ __launch_bounds__(256, 2) void proj2_kernel(
    const float* __restrict__ bias, float* __restrict__ out)
{
    gemm2_core(g_chi, g_clo, g_wthi + 3 * NE * NE, g_wtlo + 3 * NE * NE,
               blockIdx.x * 128, 1.f, nullptr, nullptr, out, bias);
}

// =====================================================================
// Attention v3: 512 threads / 16 warps, fused S&P mma loop, k-split ctx.
// smem identical 142080 B (1 CTA/SM, but 16 warps -> occ 25%).
// =====================================================================
#define ALD   40      // Q/K/R row stride (bf16), k padded 24->32, pad zeroed
#define VLD   136     // Vt row stride (bf16)
#define SLD   132     // S row stride (fp32)
#define LDC   26      // ctx partial buffer stride (fp32), overlays Q region
#define ASMEM (128*SLD*4 + 6*128*ALD*2 + 2*24*VLD*2)   // 142080 B

__global__ __launch_bounds__(512, 1) void attn3_kernel()
{
    extern __shared__ __align__(16) char smc[];
    float* S   = (float*)smc;                                  // 67584 B
    bf16* Qhi  = (bf16*)(smc + 128 * SLD * 4);
    bf16* Qlo  = Qhi + 128 * ALD;
    bf16* Khi  = Qlo + 128 * ALD;
    bf16* Klo  = Khi + 128 * ALD;
    bf16* Rhi  = Klo + 128 * ALD;
    bf16* Rlo  = Rhi + 128 * ALD;
    bf16* Vthi = Rlo + 128 * ALD;
    bf16* Vtlo = Vthi + 24 * VLD;
    float* ctxbuf = (float*)Qhi;   // 128*26*4 = 13312 B, fits in Qhi+Qlo (20480 B)

    const int bh = blockIdx.x;
    const int b = bh / NH, h = bh % NH;
    const int base = b * (TT * NE) + h * (TT * HS);   // contiguous head chunk
    const int tid = threadIdx.x;

    // ---- preamble: copy pre-split bf16 Q,K,R; transpose V ----
    {
        const int row = tid >> 2;
        const int col0 = (tid & 3) * 6;
        const int src = base + row * HS + col0;
        const int dst = row * ALD + col0;
        #pragma unroll
        for (int j = 0; j < 6; j += 2) {
            *(uint32_t*)&Qhi[dst + j] = *(const uint32_t*)&g_qhi[src + j];
            *(uint32_t*)&Qlo[dst + j] = *(const uint32_t*)&g_qlo[src + j];
            *(uint32_t*)&Khi[dst + j] = *(const uint32_t*)&g_khi[src + j];
            *(uint32_t*)&Klo[dst + j] = *(const uint32_t*)&g_klo[src + j];
        }
        const int rsrc = (127 + row) * HS + col0;
        #pragma unroll
        for (int j = 0; j < 6; j += 2) {
            *(uint32_t*)&Rhi[dst + j] = *(const uint32_t*)&g_rhi[rsrc + j];
            *(uint32_t*)&Rlo[dst + j] = *(const uint32_t*)&g_rlo[rsrc + j];
        }
        #pragma unroll
        for (int j = 0; j < 6; ++j) {
            Vthi[(col0 + j) * VLD + row] = g_vhi[src + j];
            Vtlo[(col0 + j) * VLD + row] = g_vlo[src + j];
        }
        if (tid < 128) {   // zero k-pad cols 24..31
            uint4 z4 = make_uint4(0, 0, 0, 0);
            *(uint4*)&Qhi[tid * ALD + 24] = z4;  *(uint4*)&Qlo[tid * ALD + 24] = z4;
            *(uint4*)&Khi[tid * ALD + 24] = z4;  *(uint4*)&Klo[tid * ALD + 24] = z4;
            *(uint4*)&Rhi[tid * ALD + 24] = z4;  *(uint4*)&Rlo[tid * ALD + 24] = z4;
        }
    }
    __syncthreads();

    const int w = tid >> 5, lane = tid & 31, g = lane >> 2, t = lane & 3;
    const int wm = w & 3, wn = w >> 2;     // 4 along M x 4 along N (32x32/warp)

    // ---- fused stages 1+2: accS = Q@K'^T, accP = Q@R^T (shared A frags) ----
    {
        float accS[2][4][4], accP[2][4][4];
        #pragma unroll
        for (int mt = 0; mt < 2; ++mt)
            #pragma unroll
            for (int nt = 0; nt < 4; ++nt)
                #pragma unroll
                for (int j = 0; j < 4; ++j) { accS[mt][nt][j] = 0.f; accP[mt][nt][j] = 0.f; }

        #pragma unroll 1
        for (int p = 0; p < 3; ++p) {
            const bf16* Ap  = (p == 1) ? Qlo : Qhi;
            const bf16* BpK = (p == 2) ? Klo : Khi;
            const bf16* BpR = (p == 2) ? Rlo : Rhi;
            #pragma unroll
            for (int ks = 0; ks < 2; ++ks) {
                const int k0 = ks * 16;
                uint32_t a[2][4];
                #pragma unroll
                for (int mt = 0; mt < 2; ++mt) {
                    const bf16* ab = Ap + (wm * 32 + mt * 16 + g) * ALD + k0 + 2 * t;
                    a[mt][0] = *(const uint32_t*)(ab);
                    a[mt][1] = *(const uint32_t*)(ab + 8 * ALD);
                    a[mt][2] = *(const uint32_t*)(ab + 8);
                    a[mt][3] = *(const uint32_t*)(ab + 8 * ALD + 8);
                }
                #pragma unroll
                for (int nt = 0; nt < 4; ++nt) {
                    const bf16* bk = BpK + (wn * 32 + nt * 8 + g) * ALD + k0 + 2 * t;
                    uint32_t bk0 = *(const uint32_t*)(bk);
                    uint32_t bk1 = *(const uint32_t*)(bk + 8);
                    const bf16* br = BpR + (wn * 32 + nt * 8 + g) * ALD + k0 + 2 * t;
                    uint32_t br0 = *(const uint32_t*)(br);
                    uint32_t br1 = *(const uint32_t*)(br + 8);
                    #pragma unroll
                    for (int mt = 0; mt < 2; ++mt) {
                        mma_bf16(accS[mt][nt], a[mt][0], a[mt][1], a[mt][2], a[mt][3], bk0, bk1);
                        mma_bf16(accP[mt][nt], a[mt][0], a[mt][1], a[mt][2], a[mt][3], br0, br1);
                    }
                }
            }
        }

        // write S
        #pragma unroll
        for (int mt = 0; mt < 2; ++mt)
            #pragma unroll
            for (int nt = 0; nt < 4; ++nt) {
                int row = wm * 32 + mt * 16 + g;
                int col = wn * 32 + nt * 8 + 2 * t;
                *(float2*)&S[row * SLD + col]       = make_float2(accS[mt][nt][0], accS[mt][nt][1]);
                *(float2*)&S[(row + 8) * SLD + col] = make_float2(accS[mt][nt][2], accS[mt][nt][3]);
            }
        __syncthreads();

        // scatter rel term: S[t][t-j] += P[t][j], unique (t,s) per (t,j)
        #pragma unroll
        for (int mt = 0; mt < 2; ++mt)
            #pragma unroll
            for (int nt = 0; nt < 4; ++nt) {
                int tr = wm * 32 + mt * 16 + g;
                int j0 = wn * 32 + nt * 8 + 2 * t;
                int s;
                s = tr - j0;             if (s >= 0) S[tr * SLD + s]       += accP[mt][nt][0];
                s = tr - (j0 + 1);       if (s >= 0) S[tr * SLD + s]       += accP[mt][nt][1];
                s = (tr + 8) - j0;       if (s >= 0) S[(tr + 8) * SLD + s] += accP[mt][nt][2];
                s = (tr + 8) - (j0 + 1); if (s >= 0) S[(tr + 8) * SLD + s] += accP[mt][nt][3];
            }
    }
    __syncthreads();

    // ---- softmax: 16 warps x 8 rows, causal mask, masked -> 0 ----
    {
        for (int r = 0; r < 8; ++r) {
            int trow = w * 8 + r;
            float x0 = (lane      <= trow) ? S[trow * SLD + lane     ] : -1e30f;
            float x1 = (lane + 32 <= trow) ? S[trow * SLD + lane + 32] : -1e30f;
            float x2 = (lane + 64 <= trow) ? S[trow * SLD + lane + 64] : -1e30f;
            float x3 = (lane + 96 <= trow) ? S[trow * SLD + lane + 96] : -1e30f;
            float m = fmaxf(fmaxf(x0, x1), fmaxf(x2, x3));
            #pragma unroll
            for (int o = 16; o > 0; o >>= 1)
                m = fmaxf(m, __shfl_xor_sync(0xffffffffu, m, o));
            float e0 = (lane      <= trow) ? __expf(x0 - m) : 0.f;
            float e1 = (lane + 32 <= trow) ? __expf(x1 - m) : 0.f;
            float e2 = (lane + 64 <= trow) ? __expf(x2 - m) : 0.f;
            float e3 = (lane + 96 <= trow) ? __expf(x3 - m) : 0.f;
            float ssum = e0 + e1 + e2 + e3;
            #pragma unroll
            for (int o = 16; o > 0; o >>= 1)
                ssum += __shfl_xor_sync(0xffffffffu, ssum, o);
            float inv = 1.0f / ssum;
            S[trow * SLD + lane     ] = e0 * inv;
            S[trow * SLD + lane + 32] = e1 * inv;
            S[trow * SLD + lane + 64] = e2 * inv;
            S[trow * SLD + lane + 96] = e3 * inv;
        }
    }
    __syncthreads();

    // ---- ctx = S @ V: 8 M-tiles x 2 K-halves across 16 warps ----
    {
        const int wk = w >> 3, wm8 = w & 7;   // wk: k-half, wm8: 16-row tile
        float acc[3][4];
        #pragma unroll
        for (int nt = 0; nt < 3; ++nt)
            #pragma unroll
            for (int j = 0; j < 4; ++j) acc[nt][j] = 0.f;

        #pragma unroll
        for (int ks = 0; ks < 4; ++ks) {
            const int k0 = wk * 64 + ks * 16;
            float2 p0 = *(const float2*)&S[(wm8 * 16 + g)     * SLD + k0 + 2 * t];
            float2 p1 = *(const float2*)&S[(wm8 * 16 + g + 8) * SLD + k0 + 2 * t];
            float2 p2 = *(const float2*)&S[(wm8 * 16 + g)     * SLD + k0 + 2 * t + 8];
            float2 p3 = *(const float2*)&S[(wm8 * 16 + g + 8) * SLD + k0 + 2 * t + 8];
            uint32_t ah0, al0, ah1, al1, ah2, al2, ah3, al3;
            split2(p0.x, p0.y, ah0, al0);
            split2(p1.x, p1.y, ah1, al1);
            split2(p2.x, p2.y, ah2, al2);
            split2(p3.x, p3.y, ah3, al3);
            #pragma unroll
            for (int nt = 0; nt < 3; ++nt) {
                const bf16* bhp = Vthi + (nt * 8 + g) * VLD + k0 + 2 * t;
                const bf16* blp = Vtlo + (nt * 8 + g) * VLD + k0 + 2 * t;
                uint32_t bh0 = *(const uint32_t*)(bhp);
                uint32_t bh1 = *(const uint32_t*)(bhp + 8);
                uint32_t bl0 = *(const uint32_t*)(blp);
                uint32_t bl1 = *(const uint32_t*)(blp + 8);
                mma_bf16(acc[nt], ah0, ah1, ah2, ah3, bh0, bh1);
                mma_bf16(acc[nt], al0, al1, al2, al3, bh0, bh1);
                mma_bf16(acc[nt], ah0, ah1, ah2, ah3, bl0, bl1);
            }
        }
        __syncthreads();     // Q region dead everywhere past this point

        if (wk == 1) {       // upper k-half writes partials
            #pragma unroll
            for (int nt = 0; nt < 3; ++nt) {
                int row = wm8 * 16 + g;
                int col = nt * 8 + 2 * t;
                *(float2*)&ctxbuf[row * LDC + col]       = make_float2(acc[nt][0], acc[nt][1]);
                *(float2*)&ctxbuf[(row + 8) * LDC + col] = make_float2(acc[nt][2], acc[nt][3]);
            }
        }
        __syncthreads();

        if (wk == 0) {       // lower half combines + splits to global
            #pragma unroll
            for (int nt = 0; nt < 3; ++nt) {
                int row = wm8 * 16 + g;
                int col = nt * 8 + 2 * t;
                float2 q0 = *(const float2*)&ctxbuf[row * LDC + col];
                float2 q1 = *(const float2*)&ctxbuf[(row + 8) * LDC + col];
                int idx = b * (TT * NE) + row * NE + h * HS + col;
                uint32_t hp, lp;
                split2(acc[nt][0] + q0.x, acc[nt][1] + q0.y, hp, lp);
                *(uint32_t*)&g_chi[idx] = hp;
                *(uint32_t*)&g_clo[idx] = lp;
                split2(acc[nt][2] + q1.x, acc[nt][3] + q1.y, hp, lp);
                *(uint32_t*)&g_chi[idx + 8 * NE] = hp;
                *(uint32_t*)&g_clo[idx + 8 * NE] = lp;
            }
        }
    }
}

// =====================================================================
extern "C" void kernel_launch(void* const* d_in, const int* in_sizes, int n_in,
                              void* d_out, int out_size)
{
    const float* x   = (const float*)d_in[0];
    const float* Wq  = (const float*)d_in[1];
    const float* Wk  = (const float*)d_in[2];
    const float* Wv  = (const float*)d_in[3];
    const float* rel = (const float*)d_in[4];
    const float* Wp  = (const float*)d_in[5];
    const float* bp  = (const float*)d_in[6];
    float* out = (float*)d_out;

    cudaFuncSetAttribute(qkv2_kernel,
                         cudaFuncAttributeMaxDynamicSharedMemorySize, GSMEM);
    cudaFuncSetAttribute(proj2_kernel,
                         cudaFuncAttributeMaxDynamicSharedMemorySize, GSMEM);
    cudaFuncSetAttribute(attn3_kernel,
                         cudaFuncAttributeMaxDynamicSharedMemorySize, ASMEM);

    split_x_kernel<<<(MTOT * NE) / (256 * 8), 256>>>(x);
    split_wr_kernel<<<dim3(81, 5), 256>>>(Wq, Wk, Wv, Wp, rel);

    dim3 gQ(MTOT / 128, 3);
    qkv2_kernel<<<gQ, 256, GSMEM>>>();

    attn3_kernel<<<BB * NH, 512, ASMEM>>>();

    proj2_kernel<<<MTOT / 128, 256, GSMEM>>>(bp, out);
}

// round 9
// speedup vs baseline: 1.9190x; 1.0699x over previous
#include <cstdint>
#include <cuda_runtime.h>
#include <cuda_bf16.h>

#define NH   6
#define HS   24
#define NE   144
#define TT   128
#define BB   256
#define MTOT (BB*TT)        // 32768 tokens

typedef __nv_bfloat16 bf16;

// ---------------- device scratch (allocation-free, bf16 hi/lo pairs) --------
__device__ bf16 g_qhi[MTOT*NE], g_qlo[MTOT*NE];
__device__ bf16 g_khi[MTOT*NE], g_klo[MTOT*NE];   // pre-scaled by 1/sqrt(hs)
__device__ bf16 g_vhi[MTOT*NE], g_vlo[MTOT*NE];
__device__ bf16 g_chi[MTOT*NE], g_clo[MTOT*NE];   // ctx, split
__device__ bf16 g_wthi[4*NE*NE], g_wtlo[4*NE*NE]; // W^T [n][k], q,k,v,proj
__device__ bf16 g_rhi[255*HS],   g_rlo[255*HS];   // rel_table split

// ---------------- helpers ----------------
__device__ __forceinline__ void mma_bf16(float c[4],
    uint32_t a0, uint32_t a1, uint32_t a2, uint32_t a3,
    uint32_t b0, uint32_t b1)
{
    asm volatile(
        "mma.sync.aligned.m16n8k16.row.col.f32.bf16.bf16.f32 "
        "{%0,%1,%2,%3}, {%4,%5,%6,%7}, {%8,%9}, {%0,%1,%2,%3};"
        : "+f"(c[0]), "+f"(c[1]), "+f"(c[2]), "+f"(c[3])
        : "r"(a0), "r"(a1), "r"(a2), "r"(a3), "r"(b0), "r"(b1));
}

__device__ __forceinline__ void split2(float v0, float v1, uint32_t& hi, uint32_t& lo)
{
    bf16 h0 = __float2bfloat16(v0), h1 = __float2bfloat16(v1);
    float r0 = v0 - __bfloat162float(h0), r1 = v1 - __bfloat162float(h1);
    hi = ((uint32_t)__bfloat16_as_ushort(h1) << 16) | __bfloat16_as_ushort(h0);
    lo = ((uint32_t)__bfloat16_as_ushort(__float2bfloat16(r1)) << 16)
       |  (uint32_t)__bfloat16_as_ushort(__float2bfloat16(r0));
}

// =====================================================================
// Setup: weight transpose+split and rel_table split (small)
// =====================================================================
__global__ __launch_bounds__(256) void split_wr_kernel(
    const float* __restrict__ Wq, const float* __restrict__ Wk,
    const float* __restrict__ Wv, const float* __restrict__ Wp,
    const float* __restrict__ rel)
{
    int m = blockIdx.y;
    int i = blockIdx.x * 256 + threadIdx.x;
    if (m < 4) {
        if (i >= NE * NE) return;
        const float* src = (m == 0) ? Wq : (m == 1) ? Wk : (m == 2) ? Wv : Wp;
        int k = i / NE, n = i - k * NE;
        float v = src[i];
        bf16 h = __float2bfloat16(v);
        g_wthi[m * NE * NE + n * NE + k] = h;
        g_wtlo[m * NE * NE + n * NE + k] = __float2bfloat16(v - __bfloat162float(h));
    } else {
        if (i >= 255 * HS) return;
        float v = rel[i];
        bf16 h = __float2bfloat16(v);
        g_rhi[i] = h;
        g_rlo[i] = __float2bfloat16(v - __bfloat162float(h));
    }
}

// =====================================================================
// GEMM core: out[128x144] = A @ W, K-chunked (3x48), bf16 3-term split.
// A either fp32 (split inline: Afp) or pre-split (Ahig/Alog). 2 CTAs/SM.
// =====================================================================
#define LDS2 56
#define GSMEM ((128*LDS2 + 128*LDS2 + 144*LDS2 + 144*LDS2) * 2)   // 60928

__device__ __forceinline__ void gemm2_core(
    const float* __restrict__ Afp,
    const bf16* __restrict__ Ahig, const bf16* __restrict__ Alog,
    const bf16* __restrict__ Wthi, const bf16* __restrict__ Wtlo,
    int r0, float oscale, bf16* ohi, bf16* olo,
    float* ofp, const float* __restrict__ bias)
{
    extern __shared__ __align__(16) char smc[];
    bf16* As_hi = (bf16*)smc;
    bf16* As_lo = As_hi + 128 * LDS2;
    bf16* Bs_hi = As_lo + 128 * LDS2;
    bf16* Bs_lo = Bs_hi + 144 * LDS2;

    const int tid = threadIdx.x;
    const int w = tid >> 5, lane = tid & 31, g = lane >> 2, t = lane & 3;
    const int mrow = (w & 3) * 32, ncol = (w >> 2) * 72;

    float acc[2][9][4];
    #pragma unroll
    for (int mt = 0; mt < 2; ++mt)
        #pragma unroll
        for (int nt = 0; nt < 9; ++nt)
            #pragma unroll
            for (int j = 0; j < 4; ++j) acc[mt][nt][j] = 0.f;

    #pragma unroll 1
    for (int kc = 0; kc < NE; kc += 48) {
        if (Afp) {
            for (int i = tid; i < 128 * 12; i += 256) {
                int r = i / 12, j = i - r * 12;
                float4 v = *(const float4*)&Afp[(r0 + r) * NE + kc + j * 4];
                uint32_t h0, l0, h1, l1;
                split2(v.x, v.y, h0, l0);
                split2(v.z, v.w, h1, l1);
                *(uint32_t*)&As_hi[r * LDS2 + j * 4]     = h0;
                *(uint32_t*)&As_hi[r * LDS2 + j * 4 + 2] = h1;
                *(uint32_t*)&As_lo[r * LDS2 + j * 4]     = l0;
                *(uint32_t*)&As_lo[r * LDS2 + j * 4 + 2] = l1;
            }
        } else {
            for (int i = tid; i < 128 * 6; i += 256) {
                int r = i / 6, j = i - r * 6;
                *(uint4*)&As_hi[r * LDS2 + j * 8] = *(const uint4*)&Ahig[(r0 + r) * NE + kc + j * 8];
                *(uint4*)&As_lo[r * LDS2 + j * 8] = *(const uint4*)&Alog[(r0 + r) * NE + kc + j * 8];
            }
        }
        for (int i = tid; i < 144 * 6; i += 256) {
            int r = i / 6, j = i - r * 6;
            *(uint4*)&Bs_hi[r * LDS2 + j * 8] = *(const uint4*)&Wthi[r * NE + kc + j * 8];
            *(uint4*)&Bs_lo[r * LDS2 + j * 8] = *(const uint4*)&Wtlo[r * NE + kc + j * 8];
        }
        __syncthreads();

        #pragma unroll 1
        for (int p = 0; p < 3; ++p) {
            const bf16* Ap = (p == 1) ? As_lo : As_hi;
            const bf16* Bp = (p == 2) ? Bs_lo : Bs_hi;
            #pragma unroll
            for (int ks = 0; ks < 3; ++ks) {
                const int k0 = ks * 16;
                uint32_t a[2][4];
                #pragma unroll
                for (int mt = 0; mt < 2; ++mt) {
                    const bf16* ab = Ap + (mrow + mt * 16 + g) * LDS2 + k0 + 2 * t;
                    a[mt][0] = *(const uint32_t*)(ab);
                    a[mt][1] = *(const uint32_t*)(ab + 8 * LDS2);
                    a[mt][2] = *(const uint32_t*)(ab + 8);
                    a[mt][3] = *(const uint32_t*)(ab + 8 * LDS2 + 8);
                }
                #pragma unroll
                for (int nt = 0; nt < 9; ++nt) {
                    const bf16* bb = Bp + (ncol + nt * 8 + g) * LDS2 + k0 + 2 * t;
                    uint32_t b0 = *(const uint32_t*)(bb);
                    uint32_t b1 = *(const uint32_t*)(bb + 8);
                    mma_bf16(acc[0][nt], a[0][0], a[0][1], a[0][2], a[0][3], b0, b1);
                    mma_bf16(acc[1][nt], a[1][0], a[1][1], a[1][2], a[1][3], b0, b1);
                }
            }
        }
        __syncthreads();
    }

    #pragma unroll
    for (int mt = 0; mt < 2; ++mt) {
        #pragma unroll
        for (int nt = 0; nt < 9; ++nt) {
            int row = r0 + mrow + mt * 16 + g;
            int col = ncol + nt * 8 + 2 * t;
            if (ofp) {
                float b0v = bias[col], b1v = bias[col + 1];
                ofp[row * NE + col]           = acc[mt][nt][0] + b0v;
                ofp[row * NE + col + 1]       = acc[mt][nt][1] + b1v;
                ofp[(row + 8) * NE + col]     = acc[mt][nt][2] + b0v;
                ofp[(row + 8) * NE + col + 1] = acc[mt][nt][3] + b1v;
            } else {
                uint32_t h, l;
                split2(acc[mt][nt][0] * oscale, acc[mt][nt][1] * oscale, h, l);
                *(uint32_t*)&ohi[row * NE + col] = h;
                *(uint32_t*)&olo[row * NE + col] = l;
                split2(acc[mt][nt][2] * oscale, acc[mt][nt][3] * oscale, h, l);
                *(uint32_t*)&ohi[(row + 8) * NE + col] = h;
                *(uint32_t*)&olo[(row + 8) * NE + col] = l;
            }
        }
    }
}

__global__ __launch_bounds__(256, 2) void qkv2_kernel(const float* __restrict__ x)
{
    const int z = blockIdx.y;
    const bf16* wh = g_wthi + z * NE * NE;
    const bf16* wl = g_wtlo + z * NE * NE;
    bf16 *oh, *ol;
    float sc = 1.f;
    if (z == 0)      { oh = g_qhi; ol = g_qlo; }
    else if (z == 1) { oh = g_khi; ol = g_klo; sc = 0.2041241452319315f; }
    else             { oh = g_vhi; ol = g_vlo; }
    gemm2_core(x, nullptr, nullptr, wh, wl, blockIdx.x * 128, sc, oh, ol, nullptr, nullptr);
}

__global__ __launch_bounds__(256, 2) void proj2_kernel(
    const float* __restrict__ bias, float* __restrict__ out)
{
    gemm2_core(nullptr, g_chi, g_clo, g_wthi + 3 * NE * NE, g_wtlo + 3 * NE * NE,
               blockIdx.x * 128, 1.f, nullptr, nullptr, out, bias);
}

// =====================================================================
// Attention v4: 256 threads / 8 warps, 2 CTAs/SM (smem 80640 B).
// Q/K/R fragments loaded straight from global (k-pad -> 0u operands).
// =====================================================================
#define VLD   136     // Vt row stride (bf16)
#define SLD   132     // S row stride (fp32)
#define ASMEM4 (128*SLD*4 + 2*24*VLD*2)   // 80640 B

__global__ __launch_bounds__(256, 2) void attn4_kernel()
{
    extern __shared__ __align__(16) char smc[];
    float* S   = (float*)smc;                       // [128][132] fp32
    bf16* Vthi = (bf16*)(smc + 128 * SLD * 4);      // [24][136]
    bf16* Vtlo = Vthi + 24 * VLD;

    const int bh = blockIdx.x;
    const int b = bh / NH, h = bh % NH;
    const int base = b * (TT * NE) + h * (TT * HS); // contiguous head chunk
    const int tid = threadIdx.x;

    // ---- V transpose into smem (only smem-staged operand) ----
    {
        const int row = tid >> 1, half = (tid & 1) * 12;
        const int src = base + row * HS + half;
        #pragma unroll
        for (int j = 0; j < 12; ++j) {
            Vthi[(half + j) * VLD + row] = g_vhi[src + j];
            Vtlo[(half + j) * VLD + row] = g_vlo[src + j];
        }
    }

    const int w = tid >> 5, lane = tid & 31, g = lane >> 2, t = lane & 3;
    const int wm = w & 1, wn = w >> 1;    // 2 M-halves (64) x 4 N-tiles (32)

    float acc[4][4][4];

    // ---- stage 1: S = Q @ K'^T (frags from global; ks1 upper-k zeroed) ----
    #pragma unroll
    for (int mt = 0; mt < 4; ++mt)
        #pragma unroll
        for (int nt = 0; nt < 4; ++nt)
            #pragma unroll
            for (int j = 0; j < 4; ++j) acc[mt][nt][j] = 0.f;

    #pragma unroll 1
    for (int p = 0; p < 3; ++p) {
        const bf16* Ag = ((p == 1) ? g_qlo : g_qhi) + base;
        const bf16* Bg = ((p == 2) ? g_klo : g_khi) + base;
        uint32_t a[4][6];
        #pragma unroll
        for (int mt = 0; mt < 4; ++mt) {
            const bf16* ab = Ag + (wm * 64 + mt * 16 + g) * HS + 2 * t;
            a[mt][0] = *(const uint32_t*)(ab);
            a[mt][1] = *(const uint32_t*)(ab + 8 * HS);
            a[mt][2] = *(const uint32_t*)(ab + 8);
            a[mt][3] = *(const uint32_t*)(ab + 8 * HS + 8);
            a[mt][4] = *(const uint32_t*)(ab + 16);
            a[mt][5] = *(const uint32_t*)(ab + 8 * HS + 16);
        }
        #pragma unroll
        for (int nt = 0; nt < 4; ++nt) {
            const bf16* bb = Bg + (wn * 32 + nt * 8 + g) * HS + 2 * t;
            uint32_t b0 = *(const uint32_t*)(bb);
            uint32_t b1 = *(const uint32_t*)(bb + 8);
            uint32_t b2 = *(const uint32_t*)(bb + 16);
            #pragma unroll
            for (int mt = 0; mt < 4; ++mt) {
                mma_bf16(acc[mt][nt], a[mt][0], a[mt][1], a[mt][2], a[mt][3], b0, b1);
                mma_bf16(acc[mt][nt], a[mt][4], a[mt][5], 0u, 0u, b2, 0u);
            }
        }
    }
    #pragma unroll
    for (int mt = 0; mt < 4; ++mt)
        #pragma unroll
        for (int nt = 0; nt < 4; ++nt) {
            int row = wm * 64 + mt * 16 + g;
            int col = wn * 32 + nt * 8 + 2 * t;
            *(float2*)&S[row * SLD + col]       = make_float2(acc[mt][nt][0], acc[mt][nt][1]);
            *(float2*)&S[(row + 8) * SLD + col] = make_float2(acc[mt][nt][2], acc[mt][nt][3]);
        }

    // ---- stage 2: P = Q @ R^T into same acc regs (pre-barrier overlap) ----
    #pragma unroll
    for (int mt = 0; mt < 4; ++mt)
        #pragma unroll
        for (int nt = 0; nt < 4; ++nt)
            #pragma unroll
            for (int j = 0; j < 4; ++j) acc[mt][nt][j] = 0.f;

    #pragma unroll 1
    for (int p = 0; p < 3; ++p) {
        const bf16* Ag = ((p == 1) ? g_qlo : g_qhi) + base;
        const bf16* Bg = ((p == 2) ? g_rlo : g_rhi) + 127 * HS;
        uint32_t a[4][6];
        #pragma unroll
        for (int mt = 0; mt < 4; ++mt) {
            const bf16* ab = Ag + (wm * 64 + mt * 16 + g) * HS + 2 * t;
            a[mt][0] = *(const uint32_t*)(ab);
            a[mt][1] = *(const uint32_t*)(ab + 8 * HS);
            a[mt][2] = *(const uint32_t*)(ab + 8);
            a[mt][3] = *(const uint32_t*)(ab + 8 * HS + 8);
            a[mt][4] = *(const uint32_t*)(ab + 16);
            a[mt][5] = *(const uint32_t*)(ab + 8 * HS + 16);
        }
        #pragma unroll
        for (int nt = 0; nt < 4; ++nt) {
            const bf16* bb = Bg + (wn * 32 + nt * 8 + g) * HS + 2 * t;
            uint32_t b0 = *(const uint32_t*)(bb);
            uint32_t b1 = *(const uint32_t*)(bb + 8);
            uint32_t b2 = *(const uint32_t*)(bb + 16);
            #pragma unroll
            for (int mt = 0; mt < 4; ++mt) {
                mma_bf16(acc[mt][nt], a[mt][0], a[mt][1], a[mt][2], a[mt][3], b0, b1);
                mma_bf16(acc[mt][nt], a[mt][4], a[mt][5], 0u, 0u, b2, 0u);
            }
        }
    }
    __syncthreads();   // S fully written before cross-column scatter

    // scatter rel term: S[t][t-j] += P[t][j], unique (t,s) per (t,j)
    #pragma unroll
    for (int mt = 0; mt < 4; ++mt)
        #pragma unroll
        for (int nt = 0; nt < 4; ++nt) {
            int tr = wm * 64 + mt * 16 + g;
            int j0 = wn * 32 + nt * 8 + 2 * t;
            int s;
            s = tr - j0;             if (s >= 0) S[tr * SLD + s]       += acc[mt][nt][0];
            s = tr - (j0 + 1);       if (s >= 0) S[tr * SLD + s]       += acc[mt][nt][1];
            s = (tr + 8) - j0;       if (s >= 0) S[(tr + 8) * SLD + s] += acc[mt][nt][2];
            s = (tr + 8) - (j0 + 1); if (s >= 0) S[(tr + 8) * SLD + s] += acc[mt][nt][3];
        }
    __syncthreads();

    // ---- softmax: 8 warps x 16 rows, causal mask, masked -> 0 ----
    {
        for (int r = 0; r < 16; ++r) {
            int trow = w * 16 + r;
            float x0 = (lane      <= trow) ? S[trow * SLD + lane     ] : -1e30f;
            float x1 = (lane + 32 <= trow) ? S[trow * SLD + lane + 32] : -1e30f;
            float x2 = (lane + 64 <= trow) ? S[trow * SLD + lane + 64] : -1e30f;
            float x3 = (lane + 96 <= trow) ? S[trow * SLD + lane + 96] : -1e30f;
            float m = fmaxf(fmaxf(x0, x1), fmaxf(x2, x3));
            #pragma unroll
            for (int o = 16; o > 0; o >>= 1)
                m = fmaxf(m, __shfl_xor_sync(0xffffffffu, m, o));
            float e0 = (lane      <= trow) ? __expf(x0 - m) : 0.f;
            float e1 = (lane + 32 <= trow) ? __expf(x1 - m) : 0.f;
            float e2 = (lane + 64 <= trow) ? __expf(x2 - m) : 0.f;
            float e3 = (lane + 96 <= trow) ? __expf(x3 - m) : 0.f;
            float ssum = e0 + e1 + e2 + e3;
            #pragma unroll
            for (int o = 16; o > 0; o >>= 1)
                ssum += __shfl_xor_sync(0xffffffffu, ssum, o);
            float inv = 1.0f / ssum;
            S[trow * SLD + lane     ] = e0 * inv;
            S[trow * SLD + lane + 32] = e1 * inv;
            S[trow * SLD + lane + 64] = e2 * inv;
            S[trow * SLD + lane + 96] = e3 * inv;
        }
    }
    __syncthreads();

    // ---- ctx = S @ V: warp w owns rows w*16..+16, full K=128 ----
    {
        float cacc[3][4];
        #pragma unroll
        for (int nt = 0; nt < 3; ++nt)
            #pragma unroll
            for (int j = 0; j < 4; ++j) cacc[nt][j] = 0.f;

        #pragma unroll
        for (int ks = 0; ks < 8; ++ks) {
            const int k0 = ks * 16;
            float2 p0 = *(const float2*)&S[(w * 16 + g)     * SLD + k0 + 2 * t];
            float2 p1 = *(const float2*)&S[(w * 16 + g + 8) * SLD + k0 + 2 * t];
            float2 p2 = *(const float2*)&S[(w * 16 + g)     * SLD + k0 + 2 * t + 8];
            float2 p3 = *(const float2*)&S[(w * 16 + g + 8) * SLD + k0 + 2 * t + 8];
            uint32_t ah0, al0, ah1, al1, ah2, al2, ah3, al3;
            split2(p0.x, p0.y, ah0, al0);
            split2(p1.x, p1.y, ah1, al1);
            split2(p2.x, p2.y, ah2, al2);
            split2(p3.x, p3.y, ah3, al3);
            #pragma unroll
            for (int nt = 0; nt < 3; ++nt) {
                const bf16* bhp = Vthi + (nt * 8 + g) * VLD + k0 + 2 * t;
                const bf16* blp = Vtlo + (nt * 8 + g) * VLD + k0 + 2 * t;
                uint32_t bh0 = *(const uint32_t*)(bhp);
                uint32_t bh1 = *(const uint32_t*)(bhp + 8);
                uint32_t bl0 = *(const uint32_t*)(blp);
                uint32_t bl1 = *(const uint32_t*)(blp + 8);
                mma_bf16(cacc[nt], ah0, ah1, ah2, ah3, bh0, bh1);
                mma_bf16(cacc[nt], al0, al1, al2, al3, bh0, bh1);
                mma_bf16(cacc[nt], ah0, ah1, ah2, ah3, bl0, bl1);
            }
        }

        #pragma unroll
        for (int nt = 0; nt < 3; ++nt) {
            int row = w * 16 + g;
            int col = nt * 8 + 2 * t;
            int idx = b * (TT * NE) + row * NE + h * HS + col;
            uint32_t hp, lp;
            split2(cacc[nt][0], cacc[nt][1], hp, lp);
            *(uint32_t*)&g_chi[idx] = hp;
            *(uint32_t*)&g_clo[idx] = lp;
            split2(cacc[nt][2], cacc[nt][3], hp, lp);
            *(uint32_t*)&g_chi[idx + 8 * NE] = hp;
            *(uint32_t*)&g_clo[idx + 8 * NE] = lp;
        }
    }
}

// =====================================================================
extern "C" void kernel_launch(void* const* d_in, const int* in_sizes, int n_in,
                              void* d_out, int out_size)
{
    const float* x   = (const float*)d_in[0];
    const float* Wq  = (const float*)d_in[1];
    const float* Wk  = (const float*)d_in[2];
    const float* Wv  = (const float*)d_in[3];
    const float* rel = (const float*)d_in[4];
    const float* Wp  = (const float*)d_in[5];
    const float* bp  = (const float*)d_in[6];
    float* out = (float*)d_out;

    cudaFuncSetAttribute(qkv2_kernel,
                         cudaFuncAttributeMaxDynamicSharedMemorySize, GSMEM);
    cudaFuncSetAttribute(proj2_kernel,
                         cudaFuncAttributeMaxDynamicSharedMemorySize, GSMEM);
    cudaFuncSetAttribute(attn4_kernel,
                         cudaFuncAttributeMaxDynamicSharedMemorySize, ASMEM4);

    split_wr_kernel<<<dim3(81, 5), 256>>>(Wq, Wk, Wv, Wp, rel);

    dim3 gQ(MTOT / 128, 3);
    qkv2_kernel<<<gQ, 256, GSMEM>>>(x);

    attn4_kernel<<<BB * NH, 256, ASMEM4>>>();

    proj2_kernel<<<MTOT / 128, 256, GSMEM>>>(bp, out);
}

// round 10
// speedup vs baseline: 2.2074x; 1.1503x over previous
#include <cstdint>
#include <cuda_runtime.h>
#include <cuda_bf16.h>

#define NH   6
#define HS   24
#define NE   144
#define TT   128
#define BB   256
#define MTOT (BB*TT)        // 32768 tokens

typedef __nv_bfloat16 bf16;

// ---------------- device scratch (allocation-free, bf16 hi/lo pairs) --------
__device__ bf16 g_qhi[MTOT*NE], g_qlo[MTOT*NE];
__device__ bf16 g_khi[MTOT*NE], g_klo[MTOT*NE];   // pre-scaled by 1/sqrt(hs)
__device__ bf16 g_vhi[MTOT*NE], g_vlo[MTOT*NE];
__device__ bf16 g_chi[MTOT*NE], g_clo[MTOT*NE];   // ctx, split
__device__ bf16 g_wthi[4*NE*NE], g_wtlo[4*NE*NE]; // W^T [n][k], q,k,v,proj
__device__ bf16 g_rhi[255*HS],   g_rlo[255*HS];   // rel_table split

// ---------------- helpers ----------------
__device__ __forceinline__ void mma_bf16(float c[4],
    uint32_t a0, uint32_t a1, uint32_t a2, uint32_t a3,
    uint32_t b0, uint32_t b1)
{
    asm volatile(
        "mma.sync.aligned.m16n8k16.row.col.f32.bf16.bf16.f32 "
        "{%0,%1,%2,%3}, {%4,%5,%6,%7}, {%8,%9}, {%0,%1,%2,%3};"
        : "+f"(c[0]), "+f"(c[1]), "+f"(c[2]), "+f"(c[3])
        : "r"(a0), "r"(a1), "r"(a2), "r"(a3), "r"(b0), "r"(b1));
}

__device__ __forceinline__ void split2(float v0, float v1, uint32_t& hi, uint32_t& lo)
{
    bf16 h0 = __float2bfloat16(v0), h1 = __float2bfloat16(v1);
    float r0 = v0 - __bfloat162float(h0), r1 = v1 - __bfloat162float(h1);
    hi = ((uint32_t)__bfloat16_as_ushort(h1) << 16) | __bfloat16_as_ushort(h0);
    lo = ((uint32_t)__bfloat16_as_ushort(__float2bfloat16(r1)) << 16)
       |  (uint32_t)__bfloat16_as_ushort(__float2bfloat16(r0));
}

// =====================================================================
// Setup: weight transpose+split and rel_table split (small)
// =====================================================================
__global__ __launch_bounds__(256) void split_wr_kernel(
    const float* __restrict__ Wq, const float* __restrict__ Wk,
    const float* __restrict__ Wv, const float* __restrict__ Wp,
    const float* __restrict__ rel)
{
    int m = blockIdx.y;
    int i = blockIdx.x * 256 + threadIdx.x;
    if (m < 4) {
        if (i >= NE * NE) return;
        const float* src = (m == 0) ? Wq : (m == 1) ? Wk : (m == 2) ? Wv : Wp;
        int k = i / NE, n = i - k * NE;
        float v = src[i];
        bf16 h = __float2bfloat16(v);
        g_wthi[m * NE * NE + n * NE + k] = h;
        g_wtlo[m * NE * NE + n * NE + k] = __float2bfloat16(v - __bfloat162float(h));
    } else {
        if (i >= 255 * HS) return;
        float v = rel[i];
        bf16 h = __float2bfloat16(v);
        g_rhi[i] = h;
        g_rlo[i] = __float2bfloat16(v - __bfloat162float(h));
    }
}

// =====================================================================
// GEMM core (unchanged, validated): out[128x144] = A @ W, 2 CTAs/SM
// =====================================================================
#define LDS2 56
#define GSMEM ((128*LDS2 + 128*LDS2 + 144*LDS2 + 144*LDS2) * 2)   // 60928

__device__ __forceinline__ void gemm2_core(
    const float* __restrict__ Afp,
    const bf16* __restrict__ Ahig, const bf16* __restrict__ Alog,
    const bf16* __restrict__ Wthi, const bf16* __restrict__ Wtlo,
    int r0, float oscale, bf16* ohi, bf16* olo,
    float* ofp, const float* __restrict__ bias)
{
    extern __shared__ __align__(16) char smc[];
    bf16* As_hi = (bf16*)smc;
    bf16* As_lo = As_hi + 128 * LDS2;
    bf16* Bs_hi = As_lo + 128 * LDS2;
    bf16* Bs_lo = Bs_hi + 144 * LDS2;

    const int tid = threadIdx.x;
    const int w = tid >> 5, lane = tid & 31, g = lane >> 2, t = lane & 3;
    const int mrow = (w & 3) * 32, ncol = (w >> 2) * 72;

    float acc[2][9][4];
    #pragma unroll
    for (int mt = 0; mt < 2; ++mt)
        #pragma unroll
        for (int nt = 0; nt < 9; ++nt)
            #pragma unroll
            for (int j = 0; j < 4; ++j) acc[mt][nt][j] = 0.f;

    #pragma unroll 1
    for (int kc = 0; kc < NE; kc += 48) {
        if (Afp) {
            for (int i = tid; i < 128 * 12; i += 256) {
                int r = i / 12, j = i - r * 12;
                float4 v = *(const float4*)&Afp[(r0 + r) * NE + kc + j * 4];
                uint32_t h0, l0, h1, l1;
                split2(v.x, v.y, h0, l0);
                split2(v.z, v.w, h1, l1);
                *(uint32_t*)&As_hi[r * LDS2 + j * 4]     = h0;
                *(uint32_t*)&As_hi[r * LDS2 + j * 4 + 2] = h1;
                *(uint32_t*)&As_lo[r * LDS2 + j * 4]     = l0;
                *(uint32_t*)&As_lo[r * LDS2 + j * 4 + 2] = l1;
            }
        } else {
            for (int i = tid; i < 128 * 6; i += 256) {
                int r = i / 6, j = i - r * 6;
                *(uint4*)&As_hi[r * LDS2 + j * 8] = *(const uint4*)&Ahig[(r0 + r) * NE + kc + j * 8];
                *(uint4*)&As_lo[r * LDS2 + j * 8] = *(const uint4*)&Alog[(r0 + r) * NE + kc + j * 8];
            }
        }
        for (int i = tid; i < 144 * 6; i += 256) {
            int r = i / 6, j = i - r * 6;
            *(uint4*)&Bs_hi[r * LDS2 + j * 8] = *(const uint4*)&Wthi[r * NE + kc + j * 8];
            *(uint4*)&Bs_lo[r * LDS2 + j * 8] = *(const uint4*)&Wtlo[r * NE + kc + j * 8];
        }
        __syncthreads();

        #pragma unroll 1
        for (int p = 0; p < 3; ++p) {
            const bf16* Ap = (p == 1) ? As_lo : As_hi;
            const bf16* Bp = (p == 2) ? Bs_lo : Bs_hi;
            #pragma unroll
            for (int ks = 0; ks < 3; ++ks) {
                const int k0 = ks * 16;
                uint32_t a[2][4];
                #pragma unroll
                for (int mt = 0; mt < 2; ++mt) {
                    const bf16* ab = Ap + (mrow + mt * 16 + g) * LDS2 + k0 + 2 * t;
                    a[mt][0] = *(const uint32_t*)(ab);
                    a[mt][1] = *(const uint32_t*)(ab + 8 * LDS2);
                    a[mt][2] = *(const uint32_t*)(ab + 8);
                    a[mt][3] = *(const uint32_t*)(ab + 8 * LDS2 + 8);
                }
                #pragma unroll
                for (int nt = 0; nt < 9; ++nt) {
                    const bf16* bb = Bp + (ncol + nt * 8 + g) * LDS2 + k0 + 2 * t;
                    uint32_t b0 = *(const uint32_t*)(bb);
                    uint32_t b1 = *(const uint32_t*)(bb + 8);
                    mma_bf16(acc[0][nt], a[0][0], a[0][1], a[0][2], a[0][3], b0, b1);
                    mma_bf16(acc[1][nt], a[1][0], a[1][1], a[1][2], a[1][3], b0, b1);
                }
            }
        }
        __syncthreads();
    }

    #pragma unroll
    for (int mt = 0; mt < 2; ++mt) {
        #pragma unroll
        for (int nt = 0; nt < 9; ++nt) {
            int row = r0 + mrow + mt * 16 + g;
            int col = ncol + nt * 8 + 2 * t;
            if (ofp) {
                float b0v = bias[col], b1v = bias[col + 1];
                ofp[row * NE + col]           = acc[mt][nt][0] + b0v;
                ofp[row * NE + col + 1]       = acc[mt][nt][1] + b1v;
                ofp[(row + 8) * NE + col]     = acc[mt][nt][2] + b0v;
                ofp[(row + 8) * NE + col + 1] = acc[mt][nt][3] + b1v;
            } else {
                uint32_t h, l;
                split2(acc[mt][nt][0] * oscale, acc[mt][nt][1] * oscale, h, l);
                *(uint32_t*)&ohi[row * NE + col] = h;
                *(uint32_t*)&olo[row * NE + col] = l;
                split2(acc[mt][nt][2] * oscale, acc[mt][nt][3] * oscale, h, l);
                *(uint32_t*)&ohi[(row + 8) * NE + col] = h;
                *(uint32_t*)&olo[(row + 8) * NE + col] = l;
            }
        }
    }
}

__global__ __launch_bounds__(256, 2) void qkv2_kernel(const float* __restrict__ x)
{
    const int z = blockIdx.y;
    const bf16* wh = g_wthi + z * NE * NE;
    const bf16* wl = g_wtlo + z * NE * NE;
    bf16 *oh, *ol;
    float sc = 1.f;
    if (z == 0)      { oh = g_qhi; ol = g_qlo; }
    else if (z == 1) { oh = g_khi; ol = g_klo; sc = 0.2041241452319315f; }
    else             { oh = g_vhi; ol = g_vlo; }
    gemm2_core(x, nullptr, nullptr, wh, wl, blockIdx.x * 128, sc, oh, ol, nullptr, nullptr);
}

__global__ __launch_bounds__(256, 2) void proj2_kernel(
    const float* __restrict__ bias, float* __restrict__ out)
{
    gemm2_core(nullptr, g_chi, g_clo, g_wthi + 3 * NE * NE, g_wtlo + 3 * NE * NE,
               blockIdx.x * 128, 1.f, nullptr, nullptr, out, bias);
}

// =====================================================================
// Attention v5: warp-per-16-rows, register-resident S, single barrier.
//   P = Q@R^T  -> smem (row-local, warp-private rows, __syncwarp only)
//   S = Q@K'^T in regs; rel GATHER S[t][c] += P[t][t-c]; mask+softmax in regs
//   ctx = S@V with softmaxed regs directly as A-fragments
// 256 threads / 8 warps, 2 CTAs/SM, smem 80640 B.
// =====================================================================
#define VLD   136     // Vt row stride (bf16)
#define SLD   132     // P row stride (fp32)
#define ASMEM5 (128*SLD*4 + 2*24*VLD*2)   // 80640 B

__global__ __launch_bounds__(256, 2) void attn5_kernel()
{
    extern __shared__ __align__(16) char smc[];
    float* P   = (float*)smc;                       // [128][132] fp32
    bf16* Vthi = (bf16*)(smc + 128 * SLD * 4);      // [24][136]
    bf16* Vtlo = Vthi + 24 * VLD;

    const int bh = blockIdx.x;
    const int b = bh / NH, h = bh % NH;
    const int base = b * (TT * NE) + h * (TT * HS); // contiguous head chunk
    const int tid = threadIdx.x;

    // ---- V transpose into smem ----
    {
        const int row = tid >> 1, half = (tid & 1) * 12;
        const int src = base + row * HS + half;
        #pragma unroll
        for (int j = 0; j < 12; ++j) {
            Vthi[(half + j) * VLD + row] = g_vhi[src + j];
            Vtlo[(half + j) * VLD + row] = g_vlo[src + j];
        }
    }
    __syncthreads();   // the only block barrier

    const int w = tid >> 5, lane = tid & 31, g = lane >> 2, t = lane & 3;
    const int tr  = w * 16 + g;       // warp owns rows w*16 .. w*16+15
    const int tr2 = tr + 8;

    float acc[16][4];

    // ---- pass 1: acc = P = Q @ R^T for own rows, all 128 j ----
    #pragma unroll
    for (int nt = 0; nt < 16; ++nt)
        #pragma unroll
        for (int j = 0; j < 4; ++j) acc[nt][j] = 0.f;

    #pragma unroll 1
    for (int p = 0; p < 3; ++p) {
        const bf16* Ag = ((p == 1) ? g_qlo : g_qhi) + base;
        const bf16* Bg = ((p == 2) ? g_rlo : g_rhi) + 127 * HS;
        const bf16* ab = Ag + tr * HS + 2 * t;
        uint32_t a0 = *(const uint32_t*)(ab);
        uint32_t a1 = *(const uint32_t*)(ab + 8 * HS);
        uint32_t a2 = *(const uint32_t*)(ab + 8);
        uint32_t a3 = *(const uint32_t*)(ab + 8 * HS + 8);
        uint32_t a4 = *(const uint32_t*)(ab + 16);
        uint32_t a5 = *(const uint32_t*)(ab + 8 * HS + 16);
        #pragma unroll
        for (int nt = 0; nt < 16; ++nt) {
            const bf16* bb = Bg + (nt * 8 + g) * HS + 2 * t;
            uint32_t b0 = *(const uint32_t*)(bb);
            uint32_t b1 = *(const uint32_t*)(bb + 8);
            uint32_t b2 = *(const uint32_t*)(bb + 16);
            mma_bf16(acc[nt], a0, a1, a2, a3, b0, b1);
            mma_bf16(acc[nt], a4, a5, 0u, 0u, b2, 0u);
        }
    }
    #pragma unroll
    for (int nt = 0; nt < 16; ++nt) {
        *(float2*)&P[tr  * SLD + nt * 8 + 2 * t] = make_float2(acc[nt][0], acc[nt][1]);
        *(float2*)&P[tr2 * SLD + nt * 8 + 2 * t] = make_float2(acc[nt][2], acc[nt][3]);
    }
    __syncwarp();      // P rows are warp-private: warp-level visibility suffices

    // ---- pass 2: acc = S = Q @ K'^T ----
    #pragma unroll
    for (int nt = 0; nt < 16; ++nt)
        #pragma unroll
        for (int j = 0; j < 4; ++j) acc[nt][j] = 0.f;

    #pragma unroll 1
    for (int p = 0; p < 3; ++p) {
        const bf16* Ag = ((p == 1) ? g_qlo : g_qhi) + base;
        const bf16* Bg = ((p == 2) ? g_klo : g_khi) + base;
        const bf16* ab = Ag + tr * HS + 2 * t;
        uint32_t a0 = *(const uint32_t*)(ab);
        uint32_t a1 = *(const uint32_t*)(ab + 8 * HS);
        uint32_t a2 = *(const uint32_t*)(ab + 8);
        uint32_t a3 = *(const uint32_t*)(ab + 8 * HS + 8);
        uint32_t a4 = *(const uint32_t*)(ab + 16);
        uint32_t a5 = *(const uint32_t*)(ab + 8 * HS + 16);
        #pragma unroll
        for (int nt = 0; nt < 16; ++nt) {
            const bf16* bb = Bg + (nt * 8 + g) * HS + 2 * t;
            uint32_t b0 = *(const uint32_t*)(bb);
            uint32_t b1 = *(const uint32_t*)(bb + 8);
            uint32_t b2 = *(const uint32_t*)(bb + 16);
            mma_bf16(acc[nt], a0, a1, a2, a3, b0, b1);
            mma_bf16(acc[nt], a4, a5, 0u, 0u, b2, 0u);
        }
    }

    // ---- rel gather + causal mask (register-resident) ----
    #pragma unroll
    for (int nt = 0; nt < 16; ++nt) {
        int c = nt * 8 + 2 * t;
        acc[nt][0] = (c     <= tr ) ? acc[nt][0] + P[tr  * SLD + tr  - c    ] : -1e30f;
        acc[nt][1] = (c + 1 <= tr ) ? acc[nt][1] + P[tr  * SLD + tr  - c - 1] : -1e30f;
        acc[nt][2] = (c     <= tr2) ? acc[nt][2] + P[tr2 * SLD + tr2 - c    ] : -1e30f;
        acc[nt][3] = (c + 1 <= tr2) ? acc[nt][3] + P[tr2 * SLD + tr2 - c - 1] : -1e30f;
    }

    // ---- softmax in registers: reduce over t-group (lanes g*4 + t) ----
    {
        float m1 = -1e30f, m2 = -1e30f;
        #pragma unroll
        for (int nt = 0; nt < 16; ++nt) {
            m1 = fmaxf(m1, fmaxf(acc[nt][0], acc[nt][1]));
            m2 = fmaxf(m2, fmaxf(acc[nt][2], acc[nt][3]));
        }
        m1 = fmaxf(m1, __shfl_xor_sync(0xffffffffu, m1, 1));
        m1 = fmaxf(m1, __shfl_xor_sync(0xffffffffu, m1, 2));
        m2 = fmaxf(m2, __shfl_xor_sync(0xffffffffu, m2, 1));
        m2 = fmaxf(m2, __shfl_xor_sync(0xffffffffu, m2, 2));
        float s1 = 0.f, s2 = 0.f;
        #pragma unroll
        for (int nt = 0; nt < 16; ++nt) {
            acc[nt][0] = __expf(acc[nt][0] - m1);  s1 += acc[nt][0];
            acc[nt][1] = __expf(acc[nt][1] - m1);  s1 += acc[nt][1];
            acc[nt][2] = __expf(acc[nt][2] - m2);  s2 += acc[nt][2];
            acc[nt][3] = __expf(acc[nt][3] - m2);  s2 += acc[nt][3];
        }
        s1 += __shfl_xor_sync(0xffffffffu, s1, 1);
        s1 += __shfl_xor_sync(0xffffffffu, s1, 2);
        s2 += __shfl_xor_sync(0xffffffffu, s2, 1);
        s2 += __shfl_xor_sync(0xffffffffu, s2, 2);
        float i1 = 1.0f / s1, i2 = 1.0f / s2;
        #pragma unroll
        for (int nt = 0; nt < 16; ++nt) {
            acc[nt][0] *= i1;  acc[nt][1] *= i1;
            acc[nt][2] *= i2;  acc[nt][3] *= i2;
        }
    }

    // ---- ctx = S @ V: acc tiles ARE the A-fragments ----
    {
        float cacc[3][4];
        #pragma unroll
        for (int nt = 0; nt < 3; ++nt)
            #pragma unroll
            for (int j = 0; j < 4; ++j) cacc[nt][j] = 0.f;

        #pragma unroll
        for (int ks = 0; ks < 8; ++ks) {
            const int k0 = ks * 16;
            uint32_t ah0, al0, ah1, al1, ah2, al2, ah3, al3;
            split2(acc[2*ks][0],     acc[2*ks][1],     ah0, al0);  // row g,   k 2t
            split2(acc[2*ks][2],     acc[2*ks][3],     ah1, al1);  // row g+8, k 2t
            split2(acc[2*ks+1][0],   acc[2*ks+1][1],   ah2, al2);  // row g,   k 2t+8
            split2(acc[2*ks+1][2],   acc[2*ks+1][3],   ah3, al3);  // row g+8, k 2t+8
            #pragma unroll
            for (int nt = 0; nt < 3; ++nt) {
                const bf16* bhp = Vthi + (nt * 8 + g) * VLD + k0 + 2 * t;
                const bf16* blp = Vtlo + (nt * 8 + g) * VLD + k0 + 2 * t;
                uint32_t bh0 = *(const uint32_t*)(bhp);
                uint32_t bh1 = *(const uint32_t*)(bhp + 8);
                uint32_t bl0 = *(const uint32_t*)(blp);
                uint32_t bl1 = *(const uint32_t*)(blp + 8);
                mma_bf16(cacc[nt], ah0, ah1, ah2, ah3, bh0, bh1);
                mma_bf16(cacc[nt], al0, al1, al2, al3, bh0, bh1);
                mma_bf16(cacc[nt], ah0, ah1, ah2, ah3, bl0, bl1);
            }
        }

        #pragma unroll
        for (int nt = 0; nt < 3; ++nt) {
            int col = nt * 8 + 2 * t;
            int idx = b * (TT * NE) + tr * NE + h * HS + col;
            uint32_t hp, lp;
            split2(cacc[nt][0], cacc[nt][1], hp, lp);
            *(uint32_t*)&g_chi[idx] = hp;
            *(uint32_t*)&g_clo[idx] = lp;
            split2(cacc[nt][2], cacc[nt][3], hp, lp);
            *(uint32_t*)&g_chi[idx + 8 * NE] = hp;
            *(uint32_t*)&g_clo[idx + 8 * NE] = lp;
        }
    }
}

// =====================================================================
extern "C" void kernel_launch(void* const* d_in, const int* in_sizes, int n_in,
                              void* d_out, int out_size)
{
    const float* x   = (const float*)d_in[0];
    const float* Wq  = (const float*)d_in[1];
    const float* Wk  = (const float*)d_in[2];
    const float* Wv  = (const float*)d_in[3];
    const float* rel = (const float*)d_in[4];
    const float* Wp  = (const float*)d_in[5];
    const float* bp  = (const float*)d_in[6];
    float* out = (float*)d_out;

    cudaFuncSetAttribute(qkv2_kernel,
                         cudaFuncAttributeMaxDynamicSharedMemorySize, GSMEM);
    cudaFuncSetAttribute(proj2_kernel,
                         cudaFuncAttributeMaxDynamicSharedMemorySize, GSMEM);
    cudaFuncSetAttribute(attn5_kernel,
                         cudaFuncAttributeMaxDynamicSharedMemorySize, ASMEM5);

    split_wr_kernel<<<dim3(81, 5), 256>>>(Wq, Wk, Wv, Wp, rel);

    dim3 gQ(MTOT / 128, 3);
    qkv2_kernel<<<gQ, 256, GSMEM>>>(x);

    attn5_kernel<<<BB * NH, 256, ASMEM5>>>();

    proj2_kernel<<<MTOT / 128, 256, GSMEM>>>(bp, out);
}